// round 1
// baseline (speedup 1.0000x reference)
#include <cuda_runtime.h>
#include <cuda_bf16.h>
#include <cstdint>

// Problem constants (fixed by reference setup_inputs)
#define NB      32
#define DIM     64
#define HH      32
#define WW      32
#define HW      1024            // H*W
#define KCODES  2048
#define TOKENS  32768           // N*H*W
#define TOK_TILE 128
#define CODE_TILE 128
#define NBLOCKS (TOKENS / TOK_TILE)   // 256

#define AS_STRIDE 132           // 128 tokens + 4 pad (4 mod 32 banks -> conflict free)
#define BS_STRIDE 132

__device__ float g_cnorm[KCODES];
__device__ float g_partial[2 * NBLOCKS];   // [0..255]=vq partials, [256..511]=recon partials

// ---- packed f32x2 helpers (Blackwell FFMA2) ----
__device__ __forceinline__ unsigned long long pack2(float x) {
    unsigned long long r;
    asm("mov.b64 %0, {%1, %1};" : "=l"(r) : "f"(x));
    return r;
}
__device__ __forceinline__ void fma2(unsigned long long& d, unsigned long long a,
                                     unsigned long long b) {
    asm("fma.rn.f32x2 %0, %1, %2, %0;" : "+l"(d) : "l"(a), "l"(b));
}
__device__ __forceinline__ float2 unpack2(unsigned long long v) {
    float2 r;
    asm("mov.b64 {%0, %1}, %2;" : "=f"(r.x), "=f"(r.y) : "l"(v));
    return r;
}

// ---- codebook row norms: ||e_k||^2 ----
__global__ void vq_cnorm(const float* __restrict__ cb) {
    int k = blockIdx.x * blockDim.x + threadIdx.x;
    if (k >= KCODES) return;
    const float* r = cb + (size_t)k * DIM;
    float s = 0.f;
#pragma unroll
    for (int c4 = 0; c4 < DIM / 4; ++c4) {
        float4 v = *(const float4*)(r + c4 * 4);
        s += v.x * v.x + v.y * v.y + v.z * v.z + v.w * v.w;
    }
    g_cnorm[k] = s;
}

// ---- main fused kernel: distance GEMM + argmin + epilogue ----
__global__ void __launch_bounds__(256)
vq_main(const float* __restrict__ lat, const float* __restrict__ tgt,
        const float* __restrict__ cb, const float* __restrict__ dw,
        const float* __restrict__ db) {
    extern __shared__ float sm[];
    float* As = sm;                         // [64][AS_STRIDE]  x^T tile: [k][token]
    float* Bs = sm + DIM * AS_STRIDE;       // [64][BS_STRIDE]  e^T tile: [k][code]

    __shared__ float s_dw[3 * DIM];
    __shared__ float s_db[3];

    const int tid = threadIdx.x;
    const int tx = tid & 15;                // code group   (8 codes)
    const int ty = tid >> 4;                // token group  (8 tokens)
    const int blk = blockIdx.x;
    const int n = blk >> 3;                 // image index (8 blocks per image)
    const int hw0 = (blk & 7) * TOK_TILE;   // token offset within image

    if (tid < 3 * DIM) s_dw[tid] = dw[tid];
    if (tid < 3) s_db[tid] = db[tid];

    // Load As[k][t] = latents[n][k][hw0+t]  (coalesced; conflict-free STS.128)
    {
        const float* latbase = lat + (size_t)n * DIM * HW + hw0;
        int lane = tid & 31;     // token-float4 index (0..31 -> 128 tokens)
        int cgrp = tid >> 5;     // 0..7
#pragma unroll
        for (int p = 0; p < 8; ++p) {
            int c = p * 8 + cgrp;
            float4 v = *(const float4*)(latbase + (size_t)c * HW + lane * 4);
            *(float4*)&As[c * AS_STRIDE + lane * 4] = v;
        }
    }

    float minv[8];
    int mini[8];
#pragma unroll
    for (int i = 0; i < 8; ++i) { minv[i] = 3.4e38f; mini[i] = 0; }

    for (int cc = 0; cc < KCODES; cc += CODE_TILE) {
        __syncthreads();
        // Load Bs[k][code] = cb[cc+code][k], code-major lanes -> conflict-free STS
#pragma unroll
        for (int p = 0; p < 8; ++p) {
            int l = p * 256 + tid;
            int code = l & 127;
            int kk4 = l >> 7;                     // 0..15
            float4 v = *(const float4*)(cb + (size_t)(cc + code) * DIM + kk4 * 4);
            float* dst = &Bs[(kk4 * 4) * BS_STRIDE + code];
            dst[0 * BS_STRIDE] = v.x;
            dst[1 * BS_STRIDE] = v.y;
            dst[2 * BS_STRIDE] = v.z;
            dst[3 * BS_STRIDE] = v.w;
        }
        __syncthreads();

        unsigned long long acc[4][8];
#pragma unroll
        for (int ip = 0; ip < 4; ++ip)
#pragma unroll
            for (int j = 0; j < 8; ++j) acc[ip][j] = 0ull;

#pragma unroll 16
        for (int k = 0; k < DIM; ++k) {
            const float* arow = &As[k * AS_STRIDE + ty * 8];
            ulonglong2 a01 = *(const ulonglong2*)(arow);       // tokens 0,1 | 2,3
            ulonglong2 a23 = *(const ulonglong2*)(arow + 4);   // tokens 4,5 | 6,7
            const float* brow = &Bs[k * BS_STRIDE + tx * 8];
            float4 b0 = *(const float4*)(brow);
            float4 b1 = *(const float4*)(brow + 4);
            float bb[8] = {b0.x, b0.y, b0.z, b0.w, b1.x, b1.y, b1.z, b1.w};
#pragma unroll
            for (int j = 0; j < 8; ++j) {
                unsigned long long bp = pack2(bb[j]);
                fma2(acc[0][j], a01.x, bp);
                fma2(acc[1][j], a01.y, bp);
                fma2(acc[2][j], a23.x, bp);
                fma2(acc[3][j], a23.y, bp);
            }
        }

        // d2 = ||e||^2 - 2 x.e  (||x||^2 constant per token, irrelevant to argmin)
        float4 cn0 = *(const float4*)(g_cnorm + cc + tx * 8);
        float4 cn1 = *(const float4*)(g_cnorm + cc + tx * 8 + 4);
        float cn[8] = {cn0.x, cn0.y, cn0.z, cn0.w, cn1.x, cn1.y, cn1.z, cn1.w};
#pragma unroll
        for (int ip = 0; ip < 4; ++ip) {
#pragma unroll
            for (int j = 0; j < 8; ++j) {
                float2 dot = unpack2(acc[ip][j]);
                float s0 = cn[j] - 2.0f * dot.x;
                float s1 = cn[j] - 2.0f * dot.y;
                int code = cc + tx * 8 + j;
                if (s0 < minv[2 * ip]) { minv[2 * ip] = s0; mini[2 * ip] = code; }
                if (s1 < minv[2 * ip + 1]) { minv[2 * ip + 1] = s1; mini[2 * ip + 1] = code; }
            }
        }
    }

    // ---- cross-thread argmin reduction (reuse Bs as scratch) ----
    __syncthreads();
    float* rv = Bs;                          // [16][128]
    int* ri = (int*)(Bs + 16 * 128);         // [16][128]
#pragma unroll
    for (int i = 0; i < 8; ++i) {
        rv[tx * 128 + ty * 8 + i] = minv[i];
        ri[tx * 128 + ty * 8 + i] = mini[i];
    }
    __syncthreads();

    float my_vq = 0.f, my_rc = 0.f;
    if (tid < TOK_TILE) {
        const int t = tid;
        float bv = rv[t];
        int bi = ri[t];
#pragma unroll
        for (int s = 1; s < 16; ++s) {
            float v = rv[s * 128 + t];
            int ii = ri[s * 128 + t];
            if (v < bv || (v == bv && ii < bi)) { bv = v; bi = ii; }
        }
        // epilogue: q = codebook[bi]; vq = ||x - q||^2; y = dec_w @ q + dec_b
        const float* q = cb + (size_t)bi * DIM;
        float y0 = s_db[0], y1 = s_db[1], y2 = s_db[2];
        float vq = 0.f;
#pragma unroll
        for (int c4 = 0; c4 < DIM / 4; ++c4) {
            float4 qv = *(const float4*)(q + c4 * 4);
            float qa[4] = {qv.x, qv.y, qv.z, qv.w};
#pragma unroll
            for (int r = 0; r < 4; ++r) {
                int c = c4 * 4 + r;
                float xc = As[c * AS_STRIDE + t];
                float dd = xc - qa[r];
                vq += dd * dd;
                y0 += s_dw[c] * qa[r];
                y1 += s_dw[DIM + c] * qa[r];
                y2 += s_dw[2 * DIM + c] * qa[r];
            }
        }
        const float* tg = tgt + (size_t)n * 3 * HW + hw0 + t;
        float e0 = y0 - tg[0];
        float e1 = y1 - tg[HW];
        float e2 = y2 - tg[2 * HW];
        my_vq = vq;
        my_rc = e0 * e0 + e1 * e1 + e2 * e2;
    }
    __syncthreads();
    rv[tid] = my_vq;
    rv[256 + tid] = my_rc;
    __syncthreads();
    if (tid == 0) {
        float sv = 0.f, sr = 0.f;
        for (int t = 0; t < TOK_TILE; ++t) { sv += rv[t]; sr += rv[256 + t]; }
        g_partial[blk] = sv;
        g_partial[NBLOCKS + blk] = sr;
    }
}

// ---- deterministic finalize ----
__global__ void vq_finalize(float* __restrict__ out, int out_size) {
    __shared__ float sv[NBLOCKS], sr[NBLOCKS];
    int t = threadIdx.x;
    sv[t] = g_partial[t];
    sr[t] = g_partial[NBLOCKS + t];
    __syncthreads();
    for (int s = NBLOCKS / 2; s > 0; s >>= 1) {
        if (t < s) { sv[t] += sv[t + s]; sr[t] += sr[t + s]; }
        __syncthreads();
    }
    // clear any extra output slots (out is poisoned to 0xAA)
    for (int idx = t; idx < out_size; idx += blockDim.x)
        if (idx >= 3) out[idx] = 0.f;
    if (t == 0) {
        float vq_loss = 2.0f * sv[0] / (float)(NB * DIM * HW);   // codebook + commitment
        float recon = sr[0] / (float)(NB * 3 * HW);
        if (out_size > 0) out[0] = vq_loss + recon;
        if (out_size > 1) out[1] = vq_loss;
        if (out_size > 2) out[2] = recon;
    }
}

extern "C" void kernel_launch(void* const* d_in, const int* in_sizes, int n_in,
                              void* d_out, int out_size) {
    const float* lat = (const float*)d_in[0];   // latents  (32,64,32,32)
    const float* tgt = (const float*)d_in[1];   // target   (32,3,32,32)
    const float* cb  = (const float*)d_in[2];   // codebook (2048,64)
    const float* dw  = (const float*)d_in[3];   // dec_w    (3,64)
    const float* db  = (const float*)d_in[4];   // dec_b    (3,)
    float* out = (float*)d_out;

    vq_cnorm<<<KCODES / 128, 128>>>(cb);

    int smem_bytes = (DIM * AS_STRIDE + DIM * BS_STRIDE) * (int)sizeof(float); // 67584
    cudaFuncSetAttribute(vq_main, cudaFuncAttributeMaxDynamicSharedMemorySize, smem_bytes);
    vq_main<<<NBLOCKS, 256, smem_bytes>>>(lat, tgt, cb, dw, db);

    vq_finalize<<<1, NBLOCKS>>>(out, out_size);
}

// round 3
// speedup vs baseline: 1.5425x; 1.5425x over previous
#include <cuda_runtime.h>
#include <cuda_bf16.h>
#include <cstdint>

// ---------------- problem constants ----------------
#define NB      32
#define DIM     64
#define HW      1024
#define KCODES  2048
#define TOK_TILE 128
#define NBLOCKS  256          // TOKENS / TOK_TILE
#define NTILES   16           // KCODES / 128

// ---------------- dynamic smem layout (bytes) ----------------
#define A_STRIDE 132
#define A_OFF    0u                       // fp32 A [64][132]  (33792 B)
#define B_OFF    33792u                   // 2 buffers x 64KB frag-ordered hi(32KB)+lo(32KB)
#define B_BUF    65536u
#define CN_OFF   164864u                  // 2 x 128 floats
#define DW_OFF   165888u                  // 192 floats
#define DB_OFF   166656u                  // 4 floats
#define IDX_OFF  166672u                  // 128 ints
#define RED_OFF  167184u                  // 512 floats scratch
#define SMEM_TOTAL 169232u

__device__ float g_cnorm[KCODES];
__device__ float g_partial[2 * NBLOCKS];
// fragment-ordered tf32 codebook: per tile 16384 floats = hi[8192] | lo[8192]
// hi addr within tile: fg*64 + lane*2 + i2   (fg = kk*16 + nt)
__device__ float g_cbf[NTILES * 16384];

// ---------------- helpers ----------------
__device__ __forceinline__ uint32_t smem_u32(const void* p) {
    uint32_t a;
    asm("{ .reg .u64 t; cvta.to.shared.u64 t, %1; cvt.u32.u64 %0, t; }" : "=r"(a) : "l"(p));
    return a;
}
__device__ __forceinline__ uint32_t tf32_cvt(float x) {
    uint32_t r; asm("cvt.rna.tf32.f32 %0, %1;" : "=r"(r) : "f"(x)); return r;
}
__device__ __forceinline__ void mma_tf32(float& d0, float& d1, float& d2, float& d3,
                                         uint32_t a0, uint32_t a1, uint32_t a2, uint32_t a3,
                                         uint32_t b0, uint32_t b1) {
    asm volatile(
        "mma.sync.aligned.m16n8k8.row.col.f32.tf32.tf32.f32 "
        "{%0,%1,%2,%3}, {%4,%5,%6,%7}, {%8,%9}, {%0,%1,%2,%3};"
        : "+f"(d0), "+f"(d1), "+f"(d2), "+f"(d3)
        : "r"(a0), "r"(a1), "r"(a2), "r"(a3), "r"(b0), "r"(b1));
}
__device__ __forceinline__ void cp16(uint32_t s, const void* g) {
    asm volatile("cp.async.cg.shared.global [%0], [%1], 16;" :: "r"(s), "l"(g));
}
__device__ __forceinline__ void cp_commit() {
    asm volatile("cp.async.commit_group;" ::: "memory");
}
__device__ __forceinline__ void cp_wait0() {
    asm volatile("cp.async.wait_group 0;" ::: "memory");
}

// ---------------- prep kernels ----------------
__global__ void vq_cnorm(const float* __restrict__ cb) {
    int k = blockIdx.x * blockDim.x + threadIdx.x;
    if (k >= KCODES) return;
    const float* r = cb + (size_t)k * DIM;
    float s = 0.f;
#pragma unroll
    for (int c4 = 0; c4 < DIM / 4; ++c4) {
        float4 v = *(const float4*)(r + c4 * 4);
        s += v.x * v.x + v.y * v.y + v.z * v.z + v.w * v.w;
    }
    g_cnorm[k] = s;
}

// Build fragment-ordered hi/lo tf32 codebook tiles.
// B fragment (m16n8k8 col-major): b0: row=lane%4, col=lane/4; b1: row=lane%4+4, col=lane/4.
__global__ void vq_cbprep(const float* __restrict__ cb) {
    int blk = blockIdx.x;                 // tile
    int lane = threadIdx.x & 31;
    int grp  = threadIdx.x >> 5;          // 0..7
    float* dsth = g_cbf + (size_t)blk * 16384;
    float* dstl = dsth + 8192;
#pragma unroll
    for (int it = 0; it < 16; ++it) {
        int fg = grp + it * 8;            // 0..127 = kk*16 + nt
        int kk = fg >> 4;
        int nt = fg & 15;
        int code = blk * 128 + nt * 8 + (lane >> 2);
        int k0 = kk * 8 + (lane & 3);
        const float* row = cb + (size_t)code * DIM;
#pragma unroll
        for (int i2 = 0; i2 < 2; ++i2) {
            float x = row[k0 + 4 * i2];
            uint32_t h = tf32_cvt(x);
            float rem = x - __uint_as_float(h);
            uint32_t l = tf32_cvt(rem);
            dsth[fg * 64 + lane * 2 + i2] = __uint_as_float(h);
            dstl[fg * 64 + lane * 2 + i2] = __uint_as_float(l);
        }
    }
}

// ---------------- main kernel ----------------
__global__ void __launch_bounds__(256, 1)
vq_main(const float* __restrict__ lat, const float* __restrict__ tgt,
        const float* __restrict__ cb, const float* __restrict__ dw,
        const float* __restrict__ db) {
    extern __shared__ char sm[];
    float* As = (float*)(sm + A_OFF);
    const uint32_t smem_base = smem_u32(sm);
    const int tid = threadIdx.x;
    const int lane = tid & 31;
    const int w = tid >> 5;
    const int gid = lane >> 2;           // 0..7  token-row group
    const int tig = lane & 3;            // 0..3  col group
    const int blk = blockIdx.x;
    const int n = blk >> 3;
    const int hw0 = (blk & 7) * TOK_TILE;

    if (tid < 192) ((float*)(sm + DW_OFF))[tid] = dw[tid];
    if (tid < 3)   ((float*)(sm + DB_OFF))[tid] = db[tid];

    // ---- stage A (fp32) [k][token] ----
    const float* latbase = lat + (size_t)n * DIM * HW + hw0;
    {
        int tl = tid & 31;
        int cgrp = tid >> 5;
#pragma unroll
        for (int p = 0; p < 8; ++p) {
            int c = p * 8 + cgrp;
            float4 v = *(const float4*)(latbase + (size_t)c * HW + tl * 4);
            *(float4*)&As[c * A_STRIDE + tl * 4] = v;
        }
    }

    // ---- B tile 0 + cn tile 0 via cp.async ----
    {
        const float4* src = (const float4*)(g_cbf);
        uint32_t dst = smem_base + B_OFF;
#pragma unroll 4
        for (int idx = tid; idx < 4096; idx += 256)
            cp16(dst + (uint32_t)idx * 16u, src + idx);
        if (tid < 32)
            cp16(smem_base + CN_OFF + (uint32_t)tid * 16u,
                 ((const float4*)g_cnorm) + tid);
        cp_commit();
    }
    cp_wait0();
    __syncthreads();

    // ---- build resident A fragments (hi/lo tf32) ----
    uint32_t ah[8][4], al[8][4];
    const int t0 = w * 16 + gid;
#pragma unroll
    for (int kk = 0; kk < 8; ++kk) {
        int k0 = kk * 8 + tig;
        float x0 = As[k0 * A_STRIDE + t0];
        float x1 = As[k0 * A_STRIDE + t0 + 8];
        float x2 = As[(k0 + 4) * A_STRIDE + t0];
        float x3 = As[(k0 + 4) * A_STRIDE + t0 + 8];
        ah[kk][0] = tf32_cvt(x0); al[kk][0] = tf32_cvt(x0 - __uint_as_float(ah[kk][0]));
        ah[kk][1] = tf32_cvt(x1); al[kk][1] = tf32_cvt(x1 - __uint_as_float(ah[kk][1]));
        ah[kk][2] = tf32_cvt(x2); al[kk][2] = tf32_cvt(x2 - __uint_as_float(ah[kk][2]));
        ah[kk][3] = tf32_cvt(x3); al[kk][3] = tf32_cvt(x3 - __uint_as_float(ah[kk][3]));
    }

    float minv0 = 3.4e38f, minv1 = 3.4e38f;
    int mini0 = 0, mini1 = 0;

    for (int i = 0; i < NTILES; ++i) {
        int cur = i & 1;
        int nb = cur ^ 1;
        if (i + 1 < NTILES) {
            const float4* src = (const float4*)(g_cbf + (size_t)(i + 1) * 16384);
            uint32_t dst = smem_base + B_OFF + (uint32_t)nb * B_BUF;
#pragma unroll 4
            for (int idx = tid; idx < 4096; idx += 256)
                cp16(dst + (uint32_t)idx * 16u, src + idx);
            if (tid < 32)
                cp16(smem_base + CN_OFF + (uint32_t)nb * 512u + (uint32_t)tid * 16u,
                     ((const float4*)(g_cnorm + (i + 1) * 128)) + tid);
            cp_commit();
        }

        const char* smB = sm + B_OFF + (uint32_t)cur * B_BUF;
        const float* cns = (const float*)(sm + CN_OFF + (uint32_t)cur * 512u);
        const int cbase = i * 128;

#pragma unroll
        for (int nt = 0; nt < 16; ++nt) {
            float d0 = 0.f, d1 = 0.f, d2 = 0.f, d3 = 0.f;
#pragma unroll
            for (int kk = 0; kk < 8; ++kk) {
                int fg = kk * 16 + nt;
                float2 bh = *(const float2*)(smB + ((size_t)fg * 64 + lane * 2) * 4);
                float2 bl = *(const float2*)(smB + 32768u + ((size_t)fg * 64 + lane * 2) * 4);
                uint32_t bh0 = __float_as_uint(bh.x), bh1 = __float_as_uint(bh.y);
                uint32_t bl0 = __float_as_uint(bl.x), bl1 = __float_as_uint(bl.y);
                mma_tf32(d0, d1, d2, d3, ah[kk][0], ah[kk][1], ah[kk][2], ah[kk][3], bh0, bh1);
                mma_tf32(d0, d1, d2, d3, ah[kk][0], ah[kk][1], ah[kk][2], ah[kk][3], bl0, bl1);
                mma_tf32(d0, d1, d2, d3, al[kk][0], al[kk][1], al[kk][2], al[kk][3], bh0, bh1);
            }
            // fold into argmin:  d2' = cn - 2*dot
            float2 cn2 = *(const float2*)(cns + nt * 8 + tig * 2);
            int c0 = cbase + nt * 8 + tig * 2;
            float v00 = fmaf(-2.f, d0, cn2.x);
            float v01 = fmaf(-2.f, d1, cn2.y);
            float v10 = fmaf(-2.f, d2, cn2.x);
            float v11 = fmaf(-2.f, d3, cn2.y);
            if (v00 < minv0) { minv0 = v00; mini0 = c0; }
            if (v01 < minv0) { minv0 = v01; mini0 = c0 + 1; }
            if (v10 < minv1) { minv1 = v10; mini1 = c0; }
            if (v11 < minv1) { minv1 = v11; mini1 = c0 + 1; }
        }
        cp_wait0();
        __syncthreads();
    }

    // ---- reduce argmin across the 4 col-threads of each token row ----
#pragma unroll
    for (int off = 1; off < 4; off <<= 1) {
        float ov0 = __shfl_xor_sync(0xFFFFFFFFu, minv0, off);
        int   oi0 = __shfl_xor_sync(0xFFFFFFFFu, mini0, off);
        float ov1 = __shfl_xor_sync(0xFFFFFFFFu, minv1, off);
        int   oi1 = __shfl_xor_sync(0xFFFFFFFFu, mini1, off);
        if (ov0 < minv0 || (ov0 == minv0 && oi0 < mini0)) { minv0 = ov0; mini0 = oi0; }
        if (ov1 < minv1 || (ov1 == minv1 && oi1 < mini1)) { minv1 = ov1; mini1 = oi1; }
    }
    int* s_idx = (int*)(sm + IDX_OFF);
    if (tig == 0) {
        s_idx[w * 16 + gid] = mini0;
        s_idx[w * 16 + gid + 8] = mini1;
    }
    __syncthreads();

    // ---- exact fp32 epilogue ----
    float my_vq = 0.f, my_rc = 0.f;
    if (tid < TOK_TILE) {
        int bi = s_idx[tid];
        const float* q = cb + (size_t)bi * DIM;
        const float* dws = (const float*)(sm + DW_OFF);
        const float* dbs = (const float*)(sm + DB_OFF);
        float y0 = dbs[0], y1 = dbs[1], y2 = dbs[2];
        float vq = 0.f;
#pragma unroll
        for (int c4 = 0; c4 < DIM / 4; ++c4) {
            float4 qv = *(const float4*)(q + c4 * 4);
            float qa[4] = {qv.x, qv.y, qv.z, qv.w};
#pragma unroll
            for (int r = 0; r < 4; ++r) {
                int c = c4 * 4 + r;
                float xc = As[c * A_STRIDE + tid];
                float dd = xc - qa[r];
                vq += dd * dd;
                y0 += dws[c] * qa[r];
                y1 += dws[DIM + c] * qa[r];
                y2 += dws[2 * DIM + c] * qa[r];
            }
        }
        const float* tg = tgt + (size_t)n * 3 * HW + hw0 + tid;
        float e0 = y0 - tg[0];
        float e1 = y1 - tg[HW];
        float e2 = y2 - tg[2 * HW];
        my_vq = vq;
        my_rc = e0 * e0 + e1 * e1 + e2 * e2;
    }
    __syncthreads();
    float* sv = (float*)(sm + RED_OFF);
    float* sr = sv + 256;
    sv[tid] = my_vq;
    sr[tid] = my_rc;
    __syncthreads();
    for (int s = 128; s > 0; s >>= 1) {
        if (tid < s) { sv[tid] += sv[tid + s]; sr[tid] += sr[tid + s]; }
        __syncthreads();
    }
    if (tid == 0) {
        g_partial[blk] = sv[0];
        g_partial[NBLOCKS + blk] = sr[0];
    }
}

// ---------------- deterministic finalize ----------------
__global__ void vq_finalize(float* __restrict__ out, int out_size) {
    __shared__ float sv[NBLOCKS], sr[NBLOCKS];
    int t = threadIdx.x;
    sv[t] = g_partial[t];
    sr[t] = g_partial[NBLOCKS + t];
    __syncthreads();
    for (int s = NBLOCKS / 2; s > 0; s >>= 1) {
        if (t < s) { sv[t] += sv[t + s]; sr[t] += sr[t + s]; }
        __syncthreads();
    }
    for (int idx = t; idx < out_size; idx += blockDim.x)
        if (idx >= 3) out[idx] = 0.f;
    if (t == 0) {
        float vq_loss = 2.0f * sv[0] / (float)(NB * DIM * HW);
        float recon = sr[0] / (float)(NB * 3 * HW);
        if (out_size > 0) out[0] = vq_loss + recon;
        if (out_size > 1) out[1] = vq_loss;
        if (out_size > 2) out[2] = recon;
    }
}

extern "C" void kernel_launch(void* const* d_in, const int* in_sizes, int n_in,
                              void* d_out, int out_size) {
    const float* lat = (const float*)d_in[0];
    const float* tgt = (const float*)d_in[1];
    const float* cb  = (const float*)d_in[2];
    const float* dw  = (const float*)d_in[3];
    const float* db  = (const float*)d_in[4];
    float* out = (float*)d_out;

    vq_cnorm<<<KCODES / 128, 128>>>(cb);
    vq_cbprep<<<NTILES, 256>>>(cb);

    cudaFuncSetAttribute(vq_main, cudaFuncAttributeMaxDynamicSharedMemorySize, SMEM_TOTAL);
    vq_main<<<NBLOCKS, 256, SMEM_TOTAL>>>(lat, tgt, cb, dw, db);

    vq_finalize<<<1, NBLOCKS>>>(out, out_size);
}

// round 4
// speedup vs baseline: 2.4786x; 1.6069x over previous
#include <cuda_runtime.h>
#include <cuda_fp16.h>
#include <cstdint>

// ---------------- problem constants ----------------
#define NB      32
#define DIM     64
#define HW      1024
#define KCODES  2048
#define TOK_TILE 128
#define NBLOCKS  256          // TOKENS / TOK_TILE
#define NTILES   16           // KCODES / 128

// ---------------- dynamic smem layout (bytes) ----------------
#define A_STRIDE 132
#define A_OFF    0u                       // fp32 A [64][132]  (33792 B)
#define B_OFF    33792u                   // 2 buffers x 32KB (hi 16KB | lo 16KB), frag-ordered
#define B_BUF    32768u
#define CN_OFF   99328u                   // 2 x 128 floats
#define DW_OFF   100352u                  // 192 floats
#define DB_OFF   101120u                  // 4 floats
#define IDX_OFF  101136u                  // 128 ints
#define RED_OFF  101648u                  // 512 floats scratch
#define SMEM_TOTAL 103696u

__device__ float g_cnorm[KCODES];
__device__ float g_partial[2 * NBLOCKS];
// fragment-ordered fp16 hi/lo codebook: per tile 8192 u32 = hi[4096] | lo[4096]
// within hi: addr = fg*64 + lane*2 + {0,1}   (fg = kk*16 + nt; {0,1} = b0/b1 regs)
__device__ uint32_t g_cbf[NTILES * 8192];

// ---------------- helpers ----------------
__device__ __forceinline__ uint32_t smem_u32(const void* p) {
    uint32_t a;
    asm("{ .reg .u64 t; cvta.to.shared.u64 t, %1; cvt.u32.u64 %0, t; }" : "=r"(a) : "l"(p));
    return a;
}
// 2-term fp16 split of a float pair -> packed half2 hi and lo
__device__ __forceinline__ void split2(float x, float y, uint32_t& hi, uint32_t& lo) {
    __half hx = __float2half_rn(x), hy = __float2half_rn(y);
    float rx = x - __half2float(hx), ry = y - __half2float(hy);
    __half2 h = __halves2half2(hx, hy);
    __half2 l = __floats2half2_rn(rx, ry);
    hi = *reinterpret_cast<uint32_t*>(&h);
    lo = *reinterpret_cast<uint32_t*>(&l);
}
__device__ __forceinline__ void mma_f16(float& d0, float& d1, float& d2, float& d3,
                                        const uint32_t* a, uint32_t b0, uint32_t b1) {
    asm volatile(
        "mma.sync.aligned.m16n8k16.row.col.f32.f16.f16.f32 "
        "{%0,%1,%2,%3}, {%4,%5,%6,%7}, {%8,%9}, {%0,%1,%2,%3};"
        : "+f"(d0), "+f"(d1), "+f"(d2), "+f"(d3)
        : "r"(a[0]), "r"(a[1]), "r"(a[2]), "r"(a[3]), "r"(b0), "r"(b1));
}
__device__ __forceinline__ void cp16(uint32_t s, const void* g) {
    asm volatile("cp.async.cg.shared.global [%0], [%1], 16;" :: "r"(s), "l"(g));
}
__device__ __forceinline__ void cp_commit() {
    asm volatile("cp.async.commit_group;" ::: "memory");
}
__device__ __forceinline__ void cp_wait0() {
    asm volatile("cp.async.wait_group 0;" ::: "memory");
}

// ---------------- prep: codebook norms + fp16 hi/lo fragment pack ----------------
__global__ void vq_prep(const float* __restrict__ cb) {
    int blk = blockIdx.x;                 // tile 0..15
    int tid = threadIdx.x;
    if (tid < 128) {
        int k = blk * 128 + tid;
        const float* r = cb + (size_t)k * DIM;
        float s = 0.f;
#pragma unroll
        for (int c4 = 0; c4 < DIM / 4; ++c4) {
            float4 v = *(const float4*)(r + c4 * 4);
            s += v.x * v.x + v.y * v.y + v.z * v.z + v.w * v.w;
        }
        g_cnorm[k] = s;
    }
    int lane = tid & 31;
    int grp  = tid >> 5;                  // 0..7
    uint32_t* dsth = g_cbf + (size_t)blk * 8192;
    uint32_t* dstl = dsth + 4096;
#pragma unroll
    for (int it = 0; it < 8; ++it) {
        int fg = grp * 8 + it;            // 0..63 = kk*16 + nt
        int kk = fg >> 4;
        int nt = fg & 15;
        int code = blk * 128 + nt * 8 + (lane >> 2);
        int k0 = kk * 16 + (lane & 3) * 2;
        const float* row = cb + (size_t)code * DIM;
        uint32_t h0, l0, h1, l1;
        split2(row[k0], row[k0 + 1], h0, l0);         // b0: k rows k0,k0+1
        split2(row[k0 + 8], row[k0 + 9], h1, l1);     // b1: k rows +8
        dsth[fg * 64 + lane * 2]     = h0;
        dsth[fg * 64 + lane * 2 + 1] = h1;
        dstl[fg * 64 + lane * 2]     = l0;
        dstl[fg * 64 + lane * 2 + 1] = l1;
    }
}

// ---------------- main kernel ----------------
__global__ void __launch_bounds__(256, 1)
vq_main(const float* __restrict__ lat, const float* __restrict__ tgt,
        const float* __restrict__ cb, const float* __restrict__ dw,
        const float* __restrict__ db) {
    extern __shared__ char sm[];
    float* As = (float*)(sm + A_OFF);
    const uint32_t smem_base = smem_u32(sm);
    const int tid = threadIdx.x;
    const int lane = tid & 31;
    const int w = tid >> 5;
    const int gid = lane >> 2;           // 0..7  token-row group
    const int tig = lane & 3;            // 0..3  col group
    const int blk = blockIdx.x;
    const int n = blk >> 3;
    const int hw0 = (blk & 7) * TOK_TILE;

    if (tid < 192) ((float*)(sm + DW_OFF))[tid] = dw[tid];
    if (tid < 3)   ((float*)(sm + DB_OFF))[tid] = db[tid];

    // ---- stage A (fp32) [k][token] ----
    const float* latbase = lat + (size_t)n * DIM * HW + hw0;
    {
        int tl = tid & 31;
        int cgrp = tid >> 5;
#pragma unroll
        for (int p = 0; p < 8; ++p) {
            int c = p * 8 + cgrp;
            float4 v = *(const float4*)(latbase + (size_t)c * HW + tl * 4);
            *(float4*)&As[c * A_STRIDE + tl * 4] = v;
        }
    }

    // ---- B tile 0 + cn tile 0 via cp.async ----
    {
        const float4* src = (const float4*)(g_cbf);
        uint32_t dst = smem_base + B_OFF;
#pragma unroll 4
        for (int idx = tid; idx < 2048; idx += 256)
            cp16(dst + (uint32_t)idx * 16u, src + idx);
        if (tid < 32)
            cp16(smem_base + CN_OFF + (uint32_t)tid * 16u,
                 ((const float4*)g_cnorm) + tid);
        cp_commit();
    }
    cp_wait0();
    __syncthreads();

    // ---- build resident A fragments (fp16 hi/lo, m16n8k16 row-major) ----
    uint32_t ah[4][4], al[4][4];
    const int t0 = w * 16 + gid;
#pragma unroll
    for (int kk = 0; kk < 4; ++kk) {
        int k0 = kk * 16 + tig * 2;
        float x00 = As[(k0 + 0) * A_STRIDE + t0];
        float x01 = As[(k0 + 1) * A_STRIDE + t0];
        float x10 = As[(k0 + 0) * A_STRIDE + t0 + 8];
        float x11 = As[(k0 + 1) * A_STRIDE + t0 + 8];
        float x20 = As[(k0 + 8) * A_STRIDE + t0];
        float x21 = As[(k0 + 9) * A_STRIDE + t0];
        float x30 = As[(k0 + 8) * A_STRIDE + t0 + 8];
        float x31 = As[(k0 + 9) * A_STRIDE + t0 + 8];
        split2(x00, x01, ah[kk][0], al[kk][0]);
        split2(x10, x11, ah[kk][1], al[kk][1]);
        split2(x20, x21, ah[kk][2], al[kk][2]);
        split2(x30, x31, ah[kk][3], al[kk][3]);
    }

    float minv0 = 3.4e38f, minv1 = 3.4e38f;
    int mini0 = 0, mini1 = 0;

    for (int i = 0; i < NTILES; ++i) {
        int cur = i & 1;
        int nb = cur ^ 1;
        if (i + 1 < NTILES) {
            const float4* src = (const float4*)(g_cbf + (size_t)(i + 1) * 8192);
            uint32_t dst = smem_base + B_OFF + (uint32_t)nb * B_BUF;
#pragma unroll 4
            for (int idx = tid; idx < 2048; idx += 256)
                cp16(dst + (uint32_t)idx * 16u, src + idx);
            if (tid < 32)
                cp16(smem_base + CN_OFF + (uint32_t)nb * 512u + (uint32_t)tid * 16u,
                     ((const float4*)(g_cnorm + (i + 1) * 128)) + tid);
            cp_commit();
        }

        const char* smB = sm + B_OFF + (uint32_t)cur * B_BUF;
        const float* cns = (const float*)(sm + CN_OFF + (uint32_t)cur * 512u);
        const int cbase = i * 128;

#pragma unroll
        for (int nt = 0; nt < 16; ++nt) {
            float d0 = 0.f, d1 = 0.f, d2 = 0.f, d3 = 0.f;
#pragma unroll
            for (int kk = 0; kk < 4; ++kk) {
                int fg = kk * 16 + nt;
                uint2 bh = *(const uint2*)(smB + ((size_t)fg * 64 + lane * 2) * 4);
                uint2 bl = *(const uint2*)(smB + 16384u + ((size_t)fg * 64 + lane * 2) * 4);
                mma_f16(d0, d1, d2, d3, ah[kk], bh.x, bh.y);
                mma_f16(d0, d1, d2, d3, ah[kk], bl.x, bl.y);
                mma_f16(d0, d1, d2, d3, al[kk], bh.x, bh.y);
            }
            // fold into argmin:  d2' = cn - 2*dot
            float2 cn2 = *(const float2*)(cns + nt * 8 + tig * 2);
            int c0 = cbase + nt * 8 + tig * 2;
            float v00 = fmaf(-2.f, d0, cn2.x);
            float v01 = fmaf(-2.f, d1, cn2.y);
            float v10 = fmaf(-2.f, d2, cn2.x);
            float v11 = fmaf(-2.f, d3, cn2.y);
            if (v00 < minv0) { minv0 = v00; mini0 = c0; }
            if (v01 < minv0) { minv0 = v01; mini0 = c0 + 1; }
            if (v10 < minv1) { minv1 = v10; mini1 = c0; }
            if (v11 < minv1) { minv1 = v11; mini1 = c0 + 1; }
        }
        cp_wait0();
        __syncthreads();
    }

    // ---- reduce argmin across the 4 col-threads of each token row ----
#pragma unroll
    for (int off = 1; off < 4; off <<= 1) {
        float ov0 = __shfl_xor_sync(0xFFFFFFFFu, minv0, off);
        int   oi0 = __shfl_xor_sync(0xFFFFFFFFu, mini0, off);
        float ov1 = __shfl_xor_sync(0xFFFFFFFFu, minv1, off);
        int   oi1 = __shfl_xor_sync(0xFFFFFFFFu, mini1, off);
        if (ov0 < minv0 || (ov0 == minv0 && oi0 < mini0)) { minv0 = ov0; mini0 = oi0; }
        if (ov1 < minv1 || (ov1 == minv1 && oi1 < mini1)) { minv1 = ov1; mini1 = oi1; }
    }
    int* s_idx = (int*)(sm + IDX_OFF);
    if (tig == 0) {
        s_idx[w * 16 + gid] = mini0;
        s_idx[w * 16 + gid + 8] = mini1;
    }
    __syncthreads();

    // ---- exact fp32 epilogue ----
    float my_vq = 0.f, my_rc = 0.f;
    if (tid < TOK_TILE) {
        int bi = s_idx[tid];
        const float* q = cb + (size_t)bi * DIM;
        const float* dws = (const float*)(sm + DW_OFF);
        const float* dbs = (const float*)(sm + DB_OFF);
        float y0 = dbs[0], y1 = dbs[1], y2 = dbs[2];
        float vq = 0.f;
#pragma unroll
        for (int c4 = 0; c4 < DIM / 4; ++c4) {
            float4 qv = *(const float4*)(q + c4 * 4);
            float qa[4] = {qv.x, qv.y, qv.z, qv.w};
#pragma unroll
            for (int r = 0; r < 4; ++r) {
                int c = c4 * 4 + r;
                float xc = As[c * A_STRIDE + tid];
                float dd = xc - qa[r];
                vq += dd * dd;
                y0 += dws[c] * qa[r];
                y1 += dws[DIM + c] * qa[r];
                y2 += dws[2 * DIM + c] * qa[r];
            }
        }
        const float* tg = tgt + (size_t)n * 3 * HW + hw0 + tid;
        float e0 = y0 - tg[0];
        float e1 = y1 - tg[HW];
        float e2 = y2 - tg[2 * HW];
        my_vq = vq;
        my_rc = e0 * e0 + e1 * e1 + e2 * e2;
    }
    __syncthreads();
    float* sv = (float*)(sm + RED_OFF);
    float* sr = sv + 256;
    sv[tid] = my_vq;
    sr[tid] = my_rc;
    __syncthreads();
    for (int s = 128; s > 0; s >>= 1) {
        if (tid < s) { sv[tid] += sv[tid + s]; sr[tid] += sr[tid + s]; }
        __syncthreads();
    }
    if (tid == 0) {
        g_partial[blk] = sv[0];
        g_partial[NBLOCKS + blk] = sr[0];
    }
}

// ---------------- deterministic finalize (shfl-based) ----------------
__global__ void vq_finalize(float* __restrict__ out, int out_size) {
    __shared__ float wv[8], wr[8];
    int t = threadIdx.x;              // 256
    int lane = t & 31, w = t >> 5;
    float v = g_partial[t];
    float r = g_partial[NBLOCKS + t];
#pragma unroll
    for (int off = 16; off > 0; off >>= 1) {
        v += __shfl_xor_sync(0xFFFFFFFFu, v, off);
        r += __shfl_xor_sync(0xFFFFFFFFu, r, off);
    }
    if (lane == 0) { wv[w] = v; wr[w] = r; }
    __syncthreads();
    for (int idx = t; idx < out_size; idx += blockDim.x)
        if (idx >= 3) out[idx] = 0.f;
    if (t == 0) {
        float sv = 0.f, sr = 0.f;
#pragma unroll
        for (int k = 0; k < 8; ++k) { sv += wv[k]; sr += wr[k]; }
        float vq_loss = 2.0f * sv / (float)(NB * DIM * HW);
        float recon = sr / (float)(NB * 3 * HW);
        if (out_size > 0) out[0] = vq_loss + recon;
        if (out_size > 1) out[1] = vq_loss;
        if (out_size > 2) out[2] = recon;
    }
}

extern "C" void kernel_launch(void* const* d_in, const int* in_sizes, int n_in,
                              void* d_out, int out_size) {
    const float* lat = (const float*)d_in[0];
    const float* tgt = (const float*)d_in[1];
    const float* cb  = (const float*)d_in[2];
    const float* dw  = (const float*)d_in[3];
    const float* db  = (const float*)d_in[4];
    float* out = (float*)d_out;

    vq_prep<<<NTILES, 256>>>(cb);

    cudaFuncSetAttribute(vq_main, cudaFuncAttributeMaxDynamicSharedMemorySize, SMEM_TOTAL);
    vq_main<<<NBLOCKS, 256, SMEM_TOTAL>>>(lat, tgt, cb, dw, db);

    vq_finalize<<<1, NBLOCKS>>>(out, out_size);
}

// round 5
// speedup vs baseline: 2.5407x; 1.0250x over previous
#include <cuda_runtime.h>
#include <cuda_fp16.h>
#include <cstdint>

// ---------------- problem constants ----------------
#define NB      32
#define DIM     64
#define HW      1024
#define KCODES  2048
#define TOK_TILE 128
#define NBLOCKS  256          // TOKENS / TOK_TILE
#define NTILES   16           // KCODES / 128

// ---------------- dynamic smem layout (bytes) ----------------
#define A_STRIDE 132
#define A_OFF    0u                       // fp32 A [64][132]  (33792 B)
#define B_OFF    33792u                   // 2 buffers x 32KB (hi 16KB | lo 16KB), frag-ordered
#define B_BUF    32768u
#define CN_OFF   99328u                   // 2 x 128 floats
#define DW_OFF   100352u                  // 192 floats
#define DB_OFF   101120u                  // 4 floats
#define IDX_OFF  101136u                  // 128 ints
#define RED_OFF  101648u                  // 512 floats scratch
#define SMEM_TOTAL 103696u

__device__ float g_cnorm[KCODES];
__device__ float g_partial[2 * NBLOCKS];
// fragment-ordered fp16 hi/lo codebook: per tile 8192 u32 = hi[4096] | lo[4096]
// within hi: addr = fg*64 + lane*2 + {0,1}   (fg = kk*16 + nt; {0,1} = b0/b1 regs)
__device__ uint32_t g_cbf[NTILES * 8192];

// ---------------- helpers ----------------
__device__ __forceinline__ uint32_t smem_u32(const void* p) {
    uint32_t a;
    asm("{ .reg .u64 t; cvta.to.shared.u64 t, %1; cvt.u32.u64 %0, t; }" : "=r"(a) : "l"(p));
    return a;
}
// 2-term fp16 split of a float pair -> packed half2 hi and lo
__device__ __forceinline__ void split2(float x, float y, uint32_t& hi, uint32_t& lo) {
    __half hx = __float2half_rn(x), hy = __float2half_rn(y);
    float rx = x - __half2float(hx), ry = y - __half2float(hy);
    __half2 h = __halves2half2(hx, hy);
    __half2 l = __floats2half2_rn(rx, ry);
    hi = *reinterpret_cast<uint32_t*>(&h);
    lo = *reinterpret_cast<uint32_t*>(&l);
}
__device__ __forceinline__ void mma_f16(float* d, const uint32_t* a,
                                        uint32_t b0, uint32_t b1) {
    asm volatile(
        "mma.sync.aligned.m16n8k16.row.col.f32.f16.f16.f32 "
        "{%0,%1,%2,%3}, {%4,%5,%6,%7}, {%8,%9}, {%0,%1,%2,%3};"
        : "+f"(d[0]), "+f"(d[1]), "+f"(d[2]), "+f"(d[3])
        : "r"(a[0]), "r"(a[1]), "r"(a[2]), "r"(a[3]), "r"(b0), "r"(b1));
}
__device__ __forceinline__ void cp16(uint32_t s, const void* g) {
    asm volatile("cp.async.cg.shared.global [%0], [%1], 16;" :: "r"(s), "l"(g));
}
__device__ __forceinline__ void cp_commit() {
    asm volatile("cp.async.commit_group;" ::: "memory");
}
__device__ __forceinline__ void cp_wait0() {
    asm volatile("cp.async.wait_group 0;" ::: "memory");
}

// ---------------- prep: codebook norms + fp16 hi/lo fragment pack ----------------
// grid 64: blk = tile*4 + sub.  Each block packs 16 fg groups and 32 cnorm rows.
__global__ void __launch_bounds__(256) vq_prep(const float* __restrict__ cb) {
    int blk = blockIdx.x;
    int tile = blk >> 2;
    int sub = blk & 3;
    int tid = threadIdx.x;
    int lane = tid & 31;
    int grp  = tid >> 5;                  // 0..7

    // cnorm: 32 codes per block
    if (tid < 32) {
        int k = tile * 128 + sub * 32 + tid;
        const float* r = cb + (size_t)k * DIM;
        float s = 0.f;
#pragma unroll
        for (int c4 = 0; c4 < DIM / 4; ++c4) {
            float4 v = *(const float4*)(r + c4 * 4);
            s += v.x * v.x + v.y * v.y + v.z * v.z + v.w * v.w;
        }
        g_cnorm[k] = s;
    }

    uint32_t* dsth = g_cbf + (size_t)tile * 8192;
    uint32_t* dstl = dsth + 4096;
#pragma unroll
    for (int it = 0; it < 2; ++it) {
        int fg = sub * 16 + grp * 2 + it; // 0..63 = kk*16 + nt
        int kk = fg >> 4;
        int nt = fg & 15;
        int code = tile * 128 + nt * 8 + (lane >> 2);
        int k0 = kk * 16 + (lane & 3) * 2;
        const float* row = cb + (size_t)code * DIM;
        uint32_t h0, l0, h1, l1;
        split2(row[k0], row[k0 + 1], h0, l0);         // b0: k rows k0,k0+1
        split2(row[k0 + 8], row[k0 + 9], h1, l1);     // b1: k rows +8
        dsth[fg * 64 + lane * 2]     = h0;
        dsth[fg * 64 + lane * 2 + 1] = h1;
        dstl[fg * 64 + lane * 2]     = l0;
        dstl[fg * 64 + lane * 2 + 1] = l1;
    }
}

// ---------------- main kernel ----------------
__global__ void __launch_bounds__(256, 2)
vq_main(const float* __restrict__ lat, const float* __restrict__ tgt,
        const float* __restrict__ cb, const float* __restrict__ dw,
        const float* __restrict__ db) {
    extern __shared__ char sm[];
    float* As = (float*)(sm + A_OFF);
    const uint32_t smem_base = smem_u32(sm);
    const int tid = threadIdx.x;
    const int lane = tid & 31;
    const int w = tid >> 5;
    const int gid = lane >> 2;           // 0..7  token-row group
    const int tig = lane & 3;            // 0..3  col group
    const int blk = blockIdx.x;
    const int n = blk >> 3;
    const int hw0 = (blk & 7) * TOK_TILE;

    if (tid < 192) ((float*)(sm + DW_OFF))[tid] = dw[tid];
    if (tid < 3)   ((float*)(sm + DB_OFF))[tid] = db[tid];

    // ---- stage A (fp32) [k][token] ----
    const float* latbase = lat + (size_t)n * DIM * HW + hw0;
    {
        int tl = tid & 31;
        int cgrp = tid >> 5;
#pragma unroll
        for (int p = 0; p < 8; ++p) {
            int c = p * 8 + cgrp;
            float4 v = *(const float4*)(latbase + (size_t)c * HW + tl * 4);
            *(float4*)&As[c * A_STRIDE + tl * 4] = v;
        }
    }

    // ---- B tile 0 + cn tile 0 via cp.async ----
    {
        const float4* src = (const float4*)(g_cbf);
        uint32_t dst = smem_base + B_OFF;
#pragma unroll 4
        for (int idx = tid; idx < 2048; idx += 256)
            cp16(dst + (uint32_t)idx * 16u, src + idx);
        if (tid < 32)
            cp16(smem_base + CN_OFF + (uint32_t)tid * 16u,
                 ((const float4*)g_cnorm) + tid);
        cp_commit();
    }
    cp_wait0();
    __syncthreads();

    // ---- build resident A fragments (fp16 hi/lo, m16n8k16 row-major) ----
    uint32_t ah[4][4], al[4][4];
    const int t0 = w * 16 + gid;
#pragma unroll
    for (int kk = 0; kk < 4; ++kk) {
        int k0 = kk * 16 + tig * 2;
        float x00 = As[(k0 + 0) * A_STRIDE + t0];
        float x01 = As[(k0 + 1) * A_STRIDE + t0];
        float x10 = As[(k0 + 0) * A_STRIDE + t0 + 8];
        float x11 = As[(k0 + 1) * A_STRIDE + t0 + 8];
        float x20 = As[(k0 + 8) * A_STRIDE + t0];
        float x21 = As[(k0 + 9) * A_STRIDE + t0];
        float x30 = As[(k0 + 8) * A_STRIDE + t0 + 8];
        float x31 = As[(k0 + 9) * A_STRIDE + t0 + 8];
        split2(x00, x01, ah[kk][0], al[kk][0]);
        split2(x10, x11, ah[kk][1], al[kk][1]);
        split2(x20, x21, ah[kk][2], al[kk][2]);
        split2(x30, x31, ah[kk][3], al[kk][3]);
    }

    float minv0 = 3.4e38f, minv1 = 3.4e38f;
    int mini0 = 0, mini1 = 0;

    for (int i = 0; i < NTILES; ++i) {
        int cur = i & 1;
        int nb = cur ^ 1;
        if (i + 1 < NTILES) {
            const float4* src = (const float4*)(g_cbf + (size_t)(i + 1) * 8192);
            uint32_t dst = smem_base + B_OFF + (uint32_t)nb * B_BUF;
#pragma unroll 4
            for (int idx = tid; idx < 2048; idx += 256)
                cp16(dst + (uint32_t)idx * 16u, src + idx);
            if (tid < 32)
                cp16(smem_base + CN_OFF + (uint32_t)nb * 512u + (uint32_t)tid * 16u,
                     ((const float4*)(g_cnorm + (i + 1) * 128)) + tid);
            cp_commit();
        }

        const char* smB = sm + B_OFF + (uint32_t)cur * B_BUF;
        const float* cns = (const float*)(sm + CN_OFF + (uint32_t)cur * 512u);
        const int cbase = i * 128;

#pragma unroll
        for (int nt = 0; nt < 16; ++nt) {
            // three independent accumulator chains -> 3-way HMMA ILP
            float dh[4] = {0.f, 0.f, 0.f, 0.f};
            float dm[4] = {0.f, 0.f, 0.f, 0.f};
            float dl[4] = {0.f, 0.f, 0.f, 0.f};
#pragma unroll
            for (int kk = 0; kk < 4; ++kk) {
                int fg = kk * 16 + nt;
                uint2 bh = *(const uint2*)(smB + ((size_t)fg * 64 + lane * 2) * 4);
                uint2 bl = *(const uint2*)(smB + 16384u + ((size_t)fg * 64 + lane * 2) * 4);
                mma_f16(dh, ah[kk], bh.x, bh.y);
                mma_f16(dm, ah[kk], bl.x, bl.y);
                mma_f16(dl, al[kk], bh.x, bh.y);
            }
            float d0 = dh[0] + dm[0] + dl[0];
            float d1 = dh[1] + dm[1] + dl[1];
            float d2 = dh[2] + dm[2] + dl[2];
            float d3 = dh[3] + dm[3] + dl[3];
            // fold into argmin:  d2' = cn - 2*dot
            float2 cn2 = *(const float2*)(cns + nt * 8 + tig * 2);
            int c0 = cbase + nt * 8 + tig * 2;
            float v00 = fmaf(-2.f, d0, cn2.x);
            float v01 = fmaf(-2.f, d1, cn2.y);
            float v10 = fmaf(-2.f, d2, cn2.x);
            float v11 = fmaf(-2.f, d3, cn2.y);
            if (v00 < minv0) { minv0 = v00; mini0 = c0; }
            if (v01 < minv0) { minv0 = v01; mini0 = c0 + 1; }
            if (v10 < minv1) { minv1 = v10; mini1 = c0; }
            if (v11 < minv1) { minv1 = v11; mini1 = c0 + 1; }
        }
        cp_wait0();
        __syncthreads();
    }

    // ---- reduce argmin across the 4 col-threads of each token row ----
#pragma unroll
    for (int off = 1; off < 4; off <<= 1) {
        float ov0 = __shfl_xor_sync(0xFFFFFFFFu, minv0, off);
        int   oi0 = __shfl_xor_sync(0xFFFFFFFFu, mini0, off);
        float ov1 = __shfl_xor_sync(0xFFFFFFFFu, minv1, off);
        int   oi1 = __shfl_xor_sync(0xFFFFFFFFu, mini1, off);
        if (ov0 < minv0 || (ov0 == minv0 && oi0 < mini0)) { minv0 = ov0; mini0 = oi0; }
        if (ov1 < minv1 || (ov1 == minv1 && oi1 < mini1)) { minv1 = ov1; mini1 = oi1; }
    }
    int* s_idx = (int*)(sm + IDX_OFF);
    if (tig == 0) {
        s_idx[w * 16 + gid] = mini0;
        s_idx[w * 16 + gid + 8] = mini1;
    }
    __syncthreads();

    // ---- exact fp32 epilogue ----
    float my_vq = 0.f, my_rc = 0.f;
    if (tid < TOK_TILE) {
        int bi = s_idx[tid];
        const float* q = cb + (size_t)bi * DIM;
        const float* dws = (const float*)(sm + DW_OFF);
        const float* dbs = (const float*)(sm + DB_OFF);
        float y0 = dbs[0], y1 = dbs[1], y2 = dbs[2];
        float vq = 0.f;
#pragma unroll
        for (int c4 = 0; c4 < DIM / 4; ++c4) {
            float4 qv = *(const float4*)(q + c4 * 4);
            float qa[4] = {qv.x, qv.y, qv.z, qv.w};
#pragma unroll
            for (int r = 0; r < 4; ++r) {
                int c = c4 * 4 + r;
                float xc = As[c * A_STRIDE + tid];
                float dd = xc - qa[r];
                vq += dd * dd;
                y0 += dws[c] * qa[r];
                y1 += dws[DIM + c] * qa[r];
                y2 += dws[2 * DIM + c] * qa[r];
            }
        }
        const float* tg = tgt + (size_t)n * 3 * HW + hw0 + tid;
        float e0 = y0 - tg[0];
        float e1 = y1 - tg[HW];
        float e2 = y2 - tg[2 * HW];
        my_vq = vq;
        my_rc = e0 * e0 + e1 * e1 + e2 * e2;
    }
    __syncthreads();
    float* sv = (float*)(sm + RED_OFF);
    float* sr = sv + 256;
    sv[tid] = my_vq;
    sr[tid] = my_rc;
    __syncthreads();
    for (int s = 128; s > 0; s >>= 1) {
        if (tid < s) { sv[tid] += sv[tid + s]; sr[tid] += sr[tid + s]; }
        __syncthreads();
    }
    if (tid == 0) {
        g_partial[blk] = sv[0];
        g_partial[NBLOCKS + blk] = sr[0];
    }
}

// ---------------- deterministic finalize (shfl-based) ----------------
__global__ void vq_finalize(float* __restrict__ out, int out_size) {
    __shared__ float wv[8], wr[8];
    int t = threadIdx.x;              // 256
    int lane = t & 31, w = t >> 5;
    float v = g_partial[t];
    float r = g_partial[NBLOCKS + t];
#pragma unroll
    for (int off = 16; off > 0; off >>= 1) {
        v += __shfl_xor_sync(0xFFFFFFFFu, v, off);
        r += __shfl_xor_sync(0xFFFFFFFFu, r, off);
    }
    if (lane == 0) { wv[w] = v; wr[w] = r; }
    __syncthreads();
    for (int idx = t; idx < out_size; idx += blockDim.x)
        if (idx >= 3) out[idx] = 0.f;
    if (t == 0) {
        float sv = 0.f, sr = 0.f;
#pragma unroll
        for (int k = 0; k < 8; ++k) { sv += wv[k]; sr += wr[k]; }
        float vq_loss = 2.0f * sv / (float)(NB * DIM * HW);
        float recon = sr / (float)(NB * 3 * HW);
        if (out_size > 0) out[0] = vq_loss + recon;
        if (out_size > 1) out[1] = vq_loss;
        if (out_size > 2) out[2] = recon;
    }
}

extern "C" void kernel_launch(void* const* d_in, const int* in_sizes, int n_in,
                              void* d_out, int out_size) {
    const float* lat = (const float*)d_in[0];
    const float* tgt = (const float*)d_in[1];
    const float* cb  = (const float*)d_in[2];
    const float* dw  = (const float*)d_in[3];
    const float* db  = (const float*)d_in[4];
    float* out = (float*)d_out;

    vq_prep<<<64, 256>>>(cb);

    cudaFuncSetAttribute(vq_main, cudaFuncAttributeMaxDynamicSharedMemorySize, SMEM_TOTAL);
    vq_main<<<NBLOCKS, 256, SMEM_TOTAL>>>(lat, tgt, cb, dw, db);

    vq_finalize<<<1, NBLOCKS>>>(out, out_size);
}

// round 6
// speedup vs baseline: 2.9181x; 1.1486x over previous
#include <cuda_runtime.h>
#include <cuda_fp16.h>
#include <cstdint>

// ---------------- problem constants ----------------
#define NB      32
#define DIM     64
#define HW      1024
#define KCODES  2048
#define TOK_TILE 128
#define NBLOCKS  256          // TOKENS / TOK_TILE
#define NTILES   16           // KCODES / 128
#define BMARG    0.75f        // conservative |d2' - d_hi| bound (rigorous bound ~0.25)
#define LIST_MAX 4096

// ---------------- dynamic smem layout (bytes) ----------------
#define A_STRIDE 132
#define A_OFF    0u                       // fp32 A [64][132]  (33792 B)
#define B_OFF    33792u                   // 2 buffers x 16KB hi-only frag tiles
#define B_BUF    16384u
#define CN_OFF   66560u                   // 2 x 128 floats
#define DW_OFF   67584u                   // 192 floats
#define DB_OFF   68352u                   // 4 floats
#define CNT_OFF  68368u                   // 1 u32 (+pad)
#define LIST_OFF 68384u                   // LIST_MAX u32
#define TOKMIN_OFF 84768u                 // 128 u64
#define RED_OFF  85792u                   // 512 floats
#define SMEM_TOTAL 88064u

__device__ float g_cnorm[KCODES];
__device__ float g_partial[2 * NBLOCKS];
// fragment-ordered fp16 HI codebook: per tile 4096 u32
// addr = fg*64 + lane*2 + {0,1}   (fg = kk*16 + nt; {0,1} = b0/b1 regs)
__device__ uint32_t g_cbf[NTILES * 4096];

// ---------------- helpers ----------------
__device__ __forceinline__ uint32_t smem_u32(const void* p) {
    uint32_t a;
    asm("{ .reg .u64 t; cvta.to.shared.u64 t, %1; cvt.u32.u64 %0, t; }" : "=r"(a) : "l"(p));
    return a;
}
__device__ __forceinline__ uint32_t packh2(float x, float y) {
    __half2 h = __floats2half2_rn(x, y);
    return *reinterpret_cast<uint32_t*>(&h);
}
__device__ __forceinline__ void mma_f16(float* d, const uint32_t* a,
                                        uint32_t b0, uint32_t b1) {
    asm volatile(
        "mma.sync.aligned.m16n8k16.row.col.f32.f16.f16.f32 "
        "{%0,%1,%2,%3}, {%4,%5,%6,%7}, {%8,%9}, {%0,%1,%2,%3};"
        : "+f"(d[0]), "+f"(d[1]), "+f"(d[2]), "+f"(d[3])
        : "r"(a[0]), "r"(a[1]), "r"(a[2]), "r"(a[3]), "r"(b0), "r"(b1));
}
__device__ __forceinline__ void cp16(uint32_t s, const void* g) {
    asm volatile("cp.async.cg.shared.global [%0], [%1], 16;" :: "r"(s), "l"(g));
}
__device__ __forceinline__ void cp_commit() {
    asm volatile("cp.async.commit_group;" ::: "memory");
}
__device__ __forceinline__ void cp_wait0() {
    asm volatile("cp.async.wait_group 0;" ::: "memory");
}
__device__ __forceinline__ uint32_t fkey(float v) {
    uint32_t b = __float_as_uint(v);
    return (b & 0x80000000u) ? ~b : (b | 0x80000000u);
}

// ---------------- prep: codebook norms + fp16 hi fragment pack ----------------
// grid 128: blk = tile*8 + sub. Each block packs 8 fg groups + 16 cnorm rows.
__global__ void __launch_bounds__(256) vq_prep(const float* __restrict__ cb) {
    int blk = blockIdx.x;
    int tile = blk >> 3;
    int sub = blk & 7;
    int tid = threadIdx.x;
    int lane = tid & 31;
    int grp  = tid >> 5;                  // 0..7

    if (tid < 16) {
        int k = tile * 128 + sub * 16 + tid;
        const float* r = cb + (size_t)k * DIM;
        float s = 0.f;
#pragma unroll
        for (int c4 = 0; c4 < DIM / 4; ++c4) {
            float4 v = *(const float4*)(r + c4 * 4);
            s += v.x * v.x + v.y * v.y + v.z * v.z + v.w * v.w;
        }
        g_cnorm[k] = s;
    }

    uint32_t* dsth = g_cbf + (size_t)tile * 4096;
    int fg = sub * 8 + grp;               // 0..63 = kk*16 + nt
    int kk = fg >> 4;
    int nt = fg & 15;
    int code = tile * 128 + nt * 8 + (lane >> 2);
    int k0 = kk * 16 + (lane & 3) * 2;
    const float* row = cb + (size_t)code * DIM;
    dsth[fg * 64 + lane * 2]     = packh2(row[k0], row[k0 + 1]);
    dsth[fg * 64 + lane * 2 + 1] = packh2(row[k0 + 8], row[k0 + 9]);
}

// ---------------- main kernel ----------------
__global__ void __launch_bounds__(256, 2)
vq_main(const float* __restrict__ lat, const float* __restrict__ tgt,
        const float* __restrict__ cb, const float* __restrict__ dw,
        const float* __restrict__ db) {
    extern __shared__ char sm[];
    float* As = (float*)(sm + A_OFF);
    const uint32_t smem_base = smem_u32(sm);
    uint32_t* cnt = (uint32_t*)(sm + CNT_OFF);
    uint32_t* list = (uint32_t*)(sm + LIST_OFF);
    unsigned long long* tokmin = (unsigned long long*)(sm + TOKMIN_OFF);
    const int tid = threadIdx.x;
    const int lane = tid & 31;
    const int w = tid >> 5;
    const int gid = lane >> 2;           // 0..7  token-row group
    const int tig = lane & 3;            // 0..3  col group
    const int blk = blockIdx.x;
    const int n = blk >> 3;
    const int hw0 = (blk & 7) * TOK_TILE;

    if (tid < 192) ((float*)(sm + DW_OFF))[tid] = dw[tid];
    if (tid < 3)   ((float*)(sm + DB_OFF))[tid] = db[tid];
    if (tid == 0)  *cnt = 0u;
    if (tid < 128) tokmin[tid] = ~0ull;

    // ---- stage A (fp32) [k][token] ----
    const float* latbase = lat + (size_t)n * DIM * HW + hw0;
    {
        int tl = tid & 31;
        int cgrp = tid >> 5;
#pragma unroll
        for (int p = 0; p < 8; ++p) {
            int c = p * 8 + cgrp;
            float4 v = *(const float4*)(latbase + (size_t)c * HW + tl * 4);
            *(float4*)&As[c * A_STRIDE + tl * 4] = v;
        }
    }

    // ---- preload B tile 0 + cn tile 0 ----
    {
        const float4* src = (const float4*)(g_cbf);
        uint32_t dst = smem_base + B_OFF;
#pragma unroll 4
        for (int idx = tid; idx < 1024; idx += 256)
            cp16(dst + (uint32_t)idx * 16u, src + idx);
        if (tid < 32)
            cp16(smem_base + CN_OFF + (uint32_t)tid * 16u,
                 ((const float4*)g_cnorm) + tid);
        cp_commit();
    }
    cp_wait0();
    __syncthreads();

    // ---- resident A hi fragments ----
    uint32_t ah[4][4];
    const int t0 = w * 16 + gid;
#pragma unroll
    for (int kk = 0; kk < 4; ++kk) {
        int k0 = kk * 16 + tig * 2;
        ah[kk][0] = packh2(As[(k0 + 0) * A_STRIDE + t0],     As[(k0 + 1) * A_STRIDE + t0]);
        ah[kk][1] = packh2(As[(k0 + 0) * A_STRIDE + t0 + 8], As[(k0 + 1) * A_STRIDE + t0 + 8]);
        ah[kk][2] = packh2(As[(k0 + 8) * A_STRIDE + t0],     As[(k0 + 9) * A_STRIDE + t0]);
        ah[kk][3] = packh2(As[(k0 + 8) * A_STRIDE + t0 + 8], As[(k0 + 9) * A_STRIDE + t0 + 8]);
    }

    float minv0 = 3.4e38f, minv1 = 3.4e38f;

    // 17 iterations: tiles 0..15, then tile 0 again (appends enabled from i=1)
    for (int i = 0; i <= NTILES; ++i) {
        int cur = i & 1;
        if (i < NTILES) {
            int nxt = (i + 1 == NTILES) ? 0 : i + 1;
            const float4* src = (const float4*)(g_cbf + (size_t)nxt * 4096);
            uint32_t dst = smem_base + B_OFF + (uint32_t)(cur ^ 1) * B_BUF;
#pragma unroll 4
            for (int idx = tid; idx < 1024; idx += 256)
                cp16(dst + (uint32_t)idx * 16u, src + idx);
            if (tid < 32)
                cp16(smem_base + CN_OFF + (uint32_t)(cur ^ 1) * 512u + (uint32_t)tid * 16u,
                     ((const float4*)(g_cnorm + nxt * 128)) + tid);
            cp_commit();
        }

        const char* smB = sm + B_OFF + (uint32_t)cur * B_BUF;
        const float* cns = (const float*)(sm + CN_OFF + (uint32_t)cur * 512u);
        const int ti = (i == NTILES) ? 0 : i;
        const int cbase = ti * 128;
        const bool appending = (i > 0);

#pragma unroll
        for (int nt = 0; nt < 16; ++nt) {
            float d[4] = {0.f, 0.f, 0.f, 0.f};
#pragma unroll
            for (int kk = 0; kk < 4; ++kk) {
                int fg = kk * 16 + nt;
                uint2 bh = *(const uint2*)(smB + ((size_t)fg * 64 + lane * 2) * 4);
                mma_f16(d, ah[kk], bh.x, bh.y);
            }
            float2 cn2 = *(const float2*)(cns + nt * 8 + tig * 2);
            int c0 = cbase + nt * 8 + tig * 2;
            float v00 = fmaf(-2.f, d[0], cn2.x);
            float v01 = fmaf(-2.f, d[1], cn2.y);
            float v10 = fmaf(-2.f, d[2], cn2.x);
            float v11 = fmaf(-2.f, d[3], cn2.y);
            if (appending) {
                float lim0 = minv0 + BMARG, lim1 = minv1 + BMARG;
                if (v00 < lim0) { uint32_t p = atomicAdd(cnt, 1u); if (p < LIST_MAX) list[p] = ((uint32_t)t0 << 11) | (uint32_t)c0; }
                if (v01 < lim0) { uint32_t p = atomicAdd(cnt, 1u); if (p < LIST_MAX) list[p] = ((uint32_t)t0 << 11) | (uint32_t)(c0 + 1); }
                if (v10 < lim1) { uint32_t p = atomicAdd(cnt, 1u); if (p < LIST_MAX) list[p] = ((uint32_t)(t0 + 8) << 11) | (uint32_t)c0; }
                if (v11 < lim1) { uint32_t p = atomicAdd(cnt, 1u); if (p < LIST_MAX) list[p] = ((uint32_t)(t0 + 8) << 11) | (uint32_t)(c0 + 1); }
            }
            minv0 = fminf(minv0, fminf(v00, v01));
            minv1 = fminf(minv1, fminf(v10, v11));
        }
        // combine running min across the 4 col-threads of each token row
        minv0 = fminf(minv0, __shfl_xor_sync(0xFFFFFFFFu, minv0, 1));
        minv0 = fminf(minv0, __shfl_xor_sync(0xFFFFFFFFu, minv0, 2));
        minv1 = fminf(minv1, __shfl_xor_sync(0xFFFFFFFFu, minv1, 1));
        minv1 = fminf(minv1, __shfl_xor_sync(0xFFFFFFFFu, minv1, 2));

        cp_wait0();
        __syncthreads();
    }

    // ---- exact fp32 refinement of candidates ----
    uint32_t total = *cnt;
    if (total > LIST_MAX) total = LIST_MAX;
    for (uint32_t idx = tid; idx < total; idx += 256) {
        uint32_t e = list[idx];
        int t = (int)(e >> 11);
        int c = (int)(e & 2047u);
        const float4* er = (const float4*)(cb + (size_t)c * DIM);
        float dot = 0.f;
#pragma unroll
        for (int k4 = 0; k4 < 16; ++k4) {
            float4 ev = er[k4];
            dot += ev.x * As[(k4 * 4 + 0) * A_STRIDE + t]
                 + ev.y * As[(k4 * 4 + 1) * A_STRIDE + t]
                 + ev.z * As[(k4 * 4 + 2) * A_STRIDE + t]
                 + ev.w * As[(k4 * 4 + 3) * A_STRIDE + t];
        }
        float val = g_cnorm[c] - 2.0f * dot;
        unsigned long long pk = ((unsigned long long)fkey(val) << 32) | (unsigned)c;
        atomicMin(&tokmin[t], pk);
    }
    __syncthreads();

    // ---- exact fp32 epilogue ----
    float my_vq = 0.f, my_rc = 0.f;
    if (tid < TOK_TILE) {
        int bi = (int)(tokmin[tid] & 0xFFFFFFFFu);
        const float* q = cb + (size_t)bi * DIM;
        const float* dws = (const float*)(sm + DW_OFF);
        const float* dbs = (const float*)(sm + DB_OFF);
        float y0 = dbs[0], y1 = dbs[1], y2 = dbs[2];
        float vq = 0.f;
#pragma unroll
        for (int c4 = 0; c4 < DIM / 4; ++c4) {
            float4 qv = *(const float4*)(q + c4 * 4);
            float qa[4] = {qv.x, qv.y, qv.z, qv.w};
#pragma unroll
            for (int r = 0; r < 4; ++r) {
                int c = c4 * 4 + r;
                float xc = As[c * A_STRIDE + tid];
                float dd = xc - qa[r];
                vq += dd * dd;
                y0 += dws[c] * qa[r];
                y1 += dws[DIM + c] * qa[r];
                y2 += dws[2 * DIM + c] * qa[r];
            }
        }
        const float* tg = tgt + (size_t)n * 3 * HW + hw0 + tid;
        float e0 = y0 - tg[0];
        float e1 = y1 - tg[HW];
        float e2 = y2 - tg[2 * HW];
        my_vq = vq;
        my_rc = e0 * e0 + e1 * e1 + e2 * e2;
    }
    __syncthreads();
    float* sv = (float*)(sm + RED_OFF);
    float* sr = sv + 256;
    sv[tid] = my_vq;
    sr[tid] = my_rc;
    __syncthreads();
    for (int s = 128; s > 0; s >>= 1) {
        if (tid < s) { sv[tid] += sv[tid + s]; sr[tid] += sr[tid + s]; }
        __syncthreads();
    }
    if (tid == 0) {
        g_partial[blk] = sv[0];
        g_partial[NBLOCKS + blk] = sr[0];
    }
}

// ---------------- deterministic finalize (shfl-based) ----------------
__global__ void vq_finalize(float* __restrict__ out, int out_size) {
    __shared__ float wv[8], wr[8];
    int t = threadIdx.x;              // 256
    int lane = t & 31, w = t >> 5;
    float v = g_partial[t];
    float r = g_partial[NBLOCKS + t];
#pragma unroll
    for (int off = 16; off > 0; off >>= 1) {
        v += __shfl_xor_sync(0xFFFFFFFFu, v, off);
        r += __shfl_xor_sync(0xFFFFFFFFu, r, off);
    }
    if (lane == 0) { wv[w] = v; wr[w] = r; }
    __syncthreads();
    for (int idx = t; idx < out_size; idx += blockDim.x)
        if (idx >= 3) out[idx] = 0.f;
    if (t == 0) {
        float sv = 0.f, sr = 0.f;
#pragma unroll
        for (int k = 0; k < 8; ++k) { sv += wv[k]; sr += wr[k]; }
        float vq_loss = 2.0f * sv / (float)(NB * DIM * HW);
        float recon = sr / (float)(NB * 3 * HW);
        if (out_size > 0) out[0] = vq_loss + recon;
        if (out_size > 1) out[1] = vq_loss;
        if (out_size > 2) out[2] = recon;
    }
}

extern "C" void kernel_launch(void* const* d_in, const int* in_sizes, int n_in,
                              void* d_out, int out_size) {
    const float* lat = (const float*)d_in[0];
    const float* tgt = (const float*)d_in[1];
    const float* cb  = (const float*)d_in[2];
    const float* dw  = (const float*)d_in[3];
    const float* db  = (const float*)d_in[4];
    float* out = (float*)d_out;

    vq_prep<<<128, 256>>>(cb);

    cudaFuncSetAttribute(vq_main, cudaFuncAttributeMaxDynamicSharedMemorySize, SMEM_TOTAL);
    vq_main<<<NBLOCKS, 256, SMEM_TOTAL>>>(lat, tgt, cb, dw, db);

    vq_finalize<<<1, NBLOCKS>>>(out, out_size);
}

// round 7
// speedup vs baseline: 2.9216x; 1.0012x over previous
#include <cuda_runtime.h>
#include <cuda_fp16.h>
#include <cstdint>

// ---------------- problem constants ----------------
#define NB      32
#define DIM     64
#define HW      1024
#define KCODES  2048
#define TOK_TILE 128
#define NBLOCKS  256          // TOKENS / TOK_TILE
#define NTILES   16           // KCODES / 128
#define BMARG    0.75f        // conservative |d2' - d_hi| bound (rigorous bound ~0.25)
#define LIST_MAX 4096

// ---------------- dynamic smem layout (bytes) ----------------
#define A_STRIDE 132
#define A_OFF    0u                       // fp32 A [64][132]  (33792 B)
#define B_OFF    33792u                   // 2 buffers x 16KB hi-only frag tiles
#define B_BUF    16384u
#define CN_OFF   66560u                   // 2 x 128 floats
#define DW_OFF   67584u                   // 192 floats
#define DB_OFF   68352u                   // 4 floats
#define CNT_OFF  68368u                   // 1 u32 (+pad)
#define LIST_OFF 68384u                   // LIST_MAX u32
#define TOKMIN_OFF 84768u                 // 128 u64
#define RED_OFF  85792u                   // 512 floats
#define SMEM_TOTAL 88064u

__device__ float g_cnorm[KCODES];
__device__ float g_partial[2 * NBLOCKS];
// fragment-ordered fp16 HI codebook: per tile 4096 u32
// addr = fg*64 + lane*2 + {0,1}   (fg = kk*16 + nt; {0,1} = b0/b1 regs)
__device__ uint32_t g_cbf[NTILES * 4096];

// ---------------- helpers ----------------
__device__ __forceinline__ uint32_t smem_u32(const void* p) {
    uint32_t a;
    asm("{ .reg .u64 t; cvta.to.shared.u64 t, %1; cvt.u32.u64 %0, t; }" : "=r"(a) : "l"(p));
    return a;
}
__device__ __forceinline__ uint32_t packh2(float x, float y) {
    __half2 h = __floats2half2_rn(x, y);
    return *reinterpret_cast<uint32_t*>(&h);
}
__device__ __forceinline__ void mma_f16(float* d, const uint32_t* a,
                                        uint32_t b0, uint32_t b1) {
    asm volatile(
        "mma.sync.aligned.m16n8k16.row.col.f32.f16.f16.f32 "
        "{%0,%1,%2,%3}, {%4,%5,%6,%7}, {%8,%9}, {%0,%1,%2,%3};"
        : "+f"(d[0]), "+f"(d[1]), "+f"(d[2]), "+f"(d[3])
        : "r"(a[0]), "r"(a[1]), "r"(a[2]), "r"(a[3]), "r"(b0), "r"(b1));
}
__device__ __forceinline__ void cp16(uint32_t s, const void* g) {
    asm volatile("cp.async.cg.shared.global [%0], [%1], 16;" :: "r"(s), "l"(g));
}
__device__ __forceinline__ void cp_commit() {
    asm volatile("cp.async.commit_group;" ::: "memory");
}
__device__ __forceinline__ void cp_wait0() {
    asm volatile("cp.async.wait_group 0;" ::: "memory");
}
__device__ __forceinline__ uint32_t fkey(float v) {
    uint32_t b = __float_as_uint(v);
    return (b & 0x80000000u) ? ~b : (b | 0x80000000u);
}

// ---------------- prep: codebook norms + fp16 hi fragment pack ----------------
// grid 128: blk = tile*8 + sub. Each block packs 8 fg groups + 16 cnorm rows.
__global__ void __launch_bounds__(256) vq_prep(const float* __restrict__ cb) {
    int blk = blockIdx.x;
    int tile = blk >> 3;
    int sub = blk & 7;
    int tid = threadIdx.x;
    int lane = tid & 31;
    int grp  = tid >> 5;                  // 0..7

    if (tid < 16) {
        int k = tile * 128 + sub * 16 + tid;
        const float* r = cb + (size_t)k * DIM;
        float s = 0.f;
#pragma unroll
        for (int c4 = 0; c4 < DIM / 4; ++c4) {
            float4 v = *(const float4*)(r + c4 * 4);
            s += v.x * v.x + v.y * v.y + v.z * v.z + v.w * v.w;
        }
        g_cnorm[k] = s;
    }

    uint32_t* dsth = g_cbf + (size_t)tile * 4096;
    int fg = sub * 8 + grp;               // 0..63 = kk*16 + nt
    int kk = fg >> 4;
    int nt = fg & 15;
    int code = tile * 128 + nt * 8 + (lane >> 2);
    int k0 = kk * 16 + (lane & 3) * 2;
    const float* row = cb + (size_t)code * DIM;
    dsth[fg * 64 + lane * 2]     = packh2(row[k0], row[k0 + 1]);
    dsth[fg * 64 + lane * 2 + 1] = packh2(row[k0 + 8], row[k0 + 9]);
}

// ---------------- main kernel ----------------
__global__ void __launch_bounds__(256, 2)
vq_main(const float* __restrict__ lat, const float* __restrict__ tgt,
        const float* __restrict__ cb, const float* __restrict__ dw,
        const float* __restrict__ db) {
    extern __shared__ char sm[];
    float* As = (float*)(sm + A_OFF);
    const uint32_t smem_base = smem_u32(sm);
    uint32_t* cnt = (uint32_t*)(sm + CNT_OFF);
    uint32_t* list = (uint32_t*)(sm + LIST_OFF);
    unsigned long long* tokmin = (unsigned long long*)(sm + TOKMIN_OFF);
    const int tid = threadIdx.x;
    const int lane = tid & 31;
    const int w = tid >> 5;
    const int gid = lane >> 2;           // 0..7  token-row group
    const int tig = lane & 3;            // 0..3  col group
    const int blk = blockIdx.x;
    const int n = blk >> 3;
    const int hw0 = (blk & 7) * TOK_TILE;

    if (tid < 192) ((float*)(sm + DW_OFF))[tid] = dw[tid];
    if (tid < 3)   ((float*)(sm + DB_OFF))[tid] = db[tid];
    if (tid == 0)  *cnt = 0u;
    if (tid < 128) tokmin[tid] = ~0ull;

    // ---- stage A (fp32) [k][token] ----
    const float* latbase = lat + (size_t)n * DIM * HW + hw0;
    {
        int tl = tid & 31;
        int cgrp = tid >> 5;
#pragma unroll
        for (int p = 0; p < 8; ++p) {
            int c = p * 8 + cgrp;
            float4 v = *(const float4*)(latbase + (size_t)c * HW + tl * 4);
            *(float4*)&As[c * A_STRIDE + tl * 4] = v;
        }
    }

    // ---- preload B tile 0 + cn tile 0 ----
    {
        const float4* src = (const float4*)(g_cbf);
        uint32_t dst = smem_base + B_OFF;
#pragma unroll 4
        for (int idx = tid; idx < 1024; idx += 256)
            cp16(dst + (uint32_t)idx * 16u, src + idx);
        if (tid < 32)
            cp16(smem_base + CN_OFF + (uint32_t)tid * 16u,
                 ((const float4*)g_cnorm) + tid);
        cp_commit();
    }
    cp_wait0();
    __syncthreads();

    // ---- resident A hi fragments ----
    uint32_t ah[4][4];
    const int t0 = w * 16 + gid;
#pragma unroll
    for (int kk = 0; kk < 4; ++kk) {
        int k0 = kk * 16 + tig * 2;
        ah[kk][0] = packh2(As[(k0 + 0) * A_STRIDE + t0],     As[(k0 + 1) * A_STRIDE + t0]);
        ah[kk][1] = packh2(As[(k0 + 0) * A_STRIDE + t0 + 8], As[(k0 + 1) * A_STRIDE + t0 + 8]);
        ah[kk][2] = packh2(As[(k0 + 8) * A_STRIDE + t0],     As[(k0 + 9) * A_STRIDE + t0]);
        ah[kk][3] = packh2(As[(k0 + 8) * A_STRIDE + t0 + 8], As[(k0 + 9) * A_STRIDE + t0 + 8]);
    }

    float minv0 = 3.4e38f, minv1 = 3.4e38f;

    // 17 iterations: tiles 0..15, then tile 0 again (appends enabled from i=1)
    for (int i = 0; i <= NTILES; ++i) {
        int cur = i & 1;
        if (i < NTILES) {
            int nxt = (i + 1 == NTILES) ? 0 : i + 1;
            const float4* src = (const float4*)(g_cbf + (size_t)nxt * 4096);
            uint32_t dst = smem_base + B_OFF + (uint32_t)(cur ^ 1) * B_BUF;
#pragma unroll 4
            for (int idx = tid; idx < 1024; idx += 256)
                cp16(dst + (uint32_t)idx * 16u, src + idx);
            if (tid < 32)
                cp16(smem_base + CN_OFF + (uint32_t)(cur ^ 1) * 512u + (uint32_t)tid * 16u,
                     ((const float4*)(g_cnorm + nxt * 128)) + tid);
            cp_commit();
        }

        const char* smB = sm + B_OFF + (uint32_t)cur * B_BUF;
        const float* cns = (const float*)(sm + CN_OFF + (uint32_t)cur * 512u);
        const int ti = (i == NTILES) ? 0 : i;
        const int cbase = ti * 128;
        const bool appending = (i > 0);
        const float lim0 = minv0 + BMARG, lim1 = minv1 + BMARG;

#pragma unroll
        for (int nt = 0; nt < 16; nt += 2) {
            // 4 independent HMMA chains (2 nt x 2 half-k) for latency hiding
            float dA0[4] = {0.f, 0.f, 0.f, 0.f};
            float dA1[4] = {0.f, 0.f, 0.f, 0.f};
            float dB0[4] = {0.f, 0.f, 0.f, 0.f};
            float dB1[4] = {0.f, 0.f, 0.f, 0.f};
            uint2 bA[4], bB[4];
#pragma unroll
            for (int kk = 0; kk < 4; ++kk) {
                bA[kk] = *(const uint2*)(smB + ((size_t)(kk * 16 + nt) * 64 + lane * 2) * 4);
                bB[kk] = *(const uint2*)(smB + ((size_t)(kk * 16 + nt + 1) * 64 + lane * 2) * 4);
            }
            mma_f16(dA0, ah[0], bA[0].x, bA[0].y);
            mma_f16(dB0, ah[0], bB[0].x, bB[0].y);
            mma_f16(dA1, ah[2], bA[2].x, bA[2].y);
            mma_f16(dB1, ah[2], bB[2].x, bB[2].y);
            mma_f16(dA0, ah[1], bA[1].x, bA[1].y);
            mma_f16(dB0, ah[1], bB[1].x, bB[1].y);
            mma_f16(dA1, ah[3], bA[3].x, bA[3].y);
            mma_f16(dB1, ah[3], bB[3].x, bB[3].y);

            float2 cnA = *(const float2*)(cns + nt * 8 + tig * 2);
            float2 cnB = *(const float2*)(cns + (nt + 1) * 8 + tig * 2);
            int cA = cbase + nt * 8 + tig * 2;
            int cB = cA + 8;
            float vA0 = fmaf(-2.f, dA0[0] + dA1[0], cnA.x);
            float vA1 = fmaf(-2.f, dA0[1] + dA1[1], cnA.y);
            float vA2 = fmaf(-2.f, dA0[2] + dA1[2], cnA.x);
            float vA3 = fmaf(-2.f, dA0[3] + dA1[3], cnA.y);
            float vB0 = fmaf(-2.f, dB0[0] + dB1[0], cnB.x);
            float vB1 = fmaf(-2.f, dB0[1] + dB1[1], cnB.y);
            float vB2 = fmaf(-2.f, dB0[2] + dB1[2], cnB.x);
            float vB3 = fmaf(-2.f, dB0[3] + dB1[3], cnB.y);
            if (appending) {
                if (vA0 < lim0) { uint32_t p = atomicAdd(cnt, 1u); if (p < LIST_MAX) list[p] = ((uint32_t)t0 << 11) | (uint32_t)cA; }
                if (vA1 < lim0) { uint32_t p = atomicAdd(cnt, 1u); if (p < LIST_MAX) list[p] = ((uint32_t)t0 << 11) | (uint32_t)(cA + 1); }
                if (vA2 < lim1) { uint32_t p = atomicAdd(cnt, 1u); if (p < LIST_MAX) list[p] = ((uint32_t)(t0 + 8) << 11) | (uint32_t)cA; }
                if (vA3 < lim1) { uint32_t p = atomicAdd(cnt, 1u); if (p < LIST_MAX) list[p] = ((uint32_t)(t0 + 8) << 11) | (uint32_t)(cA + 1); }
                if (vB0 < lim0) { uint32_t p = atomicAdd(cnt, 1u); if (p < LIST_MAX) list[p] = ((uint32_t)t0 << 11) | (uint32_t)cB; }
                if (vB1 < lim0) { uint32_t p = atomicAdd(cnt, 1u); if (p < LIST_MAX) list[p] = ((uint32_t)t0 << 11) | (uint32_t)(cB + 1); }
                if (vB2 < lim1) { uint32_t p = atomicAdd(cnt, 1u); if (p < LIST_MAX) list[p] = ((uint32_t)(t0 + 8) << 11) | (uint32_t)cB; }
                if (vB3 < lim1) { uint32_t p = atomicAdd(cnt, 1u); if (p < LIST_MAX) list[p] = ((uint32_t)(t0 + 8) << 11) | (uint32_t)(cB + 1); }
            }
            minv0 = fminf(minv0, fminf(fminf(vA0, vA1), fminf(vB0, vB1)));
            minv1 = fminf(minv1, fminf(fminf(vA2, vA3), fminf(vB2, vB3)));
        }
        // combine running min across the 4 col-threads of each token row
        minv0 = fminf(minv0, __shfl_xor_sync(0xFFFFFFFFu, minv0, 1));
        minv0 = fminf(minv0, __shfl_xor_sync(0xFFFFFFFFu, minv0, 2));
        minv1 = fminf(minv1, __shfl_xor_sync(0xFFFFFFFFu, minv1, 1));
        minv1 = fminf(minv1, __shfl_xor_sync(0xFFFFFFFFu, minv1, 2));

        cp_wait0();
        __syncthreads();
    }

    // ---- exact fp32 refinement of candidates ----
    uint32_t total = *cnt;
    if (total > LIST_MAX) total = LIST_MAX;
    for (uint32_t idx = tid; idx < total; idx += 256) {
        uint32_t e = list[idx];
        int t = (int)(e >> 11);
        int c = (int)(e & 2047u);
        const float4* er = (const float4*)(cb + (size_t)c * DIM);
        float dot = 0.f;
#pragma unroll
        for (int k4 = 0; k4 < 16; ++k4) {
            float4 ev = er[k4];
            dot += ev.x * As[(k4 * 4 + 0) * A_STRIDE + t]
                 + ev.y * As[(k4 * 4 + 1) * A_STRIDE + t]
                 + ev.z * As[(k4 * 4 + 2) * A_STRIDE + t]
                 + ev.w * As[(k4 * 4 + 3) * A_STRIDE + t];
        }
        float val = g_cnorm[c] - 2.0f * dot;
        unsigned long long pk = ((unsigned long long)fkey(val) << 32) | (unsigned)c;
        atomicMin(&tokmin[t], pk);
    }
    __syncthreads();

    // ---- exact fp32 epilogue ----
    float my_vq = 0.f, my_rc = 0.f;
    if (tid < TOK_TILE) {
        int bi = (int)(tokmin[tid] & 0xFFFFFFFFu);
        const float* q = cb + (size_t)bi * DIM;
        const float* dws = (const float*)(sm + DW_OFF);
        const float* dbs = (const float*)(sm + DB_OFF);
        float y0 = dbs[0], y1 = dbs[1], y2 = dbs[2];
        float vq = 0.f;
#pragma unroll
        for (int c4 = 0; c4 < DIM / 4; ++c4) {
            float4 qv = *(const float4*)(q + c4 * 4);
            float qa[4] = {qv.x, qv.y, qv.z, qv.w};
#pragma unroll
            for (int r = 0; r < 4; ++r) {
                int c = c4 * 4 + r;
                float xc = As[c * A_STRIDE + tid];
                float dd = xc - qa[r];
                vq += dd * dd;
                y0 += dws[c] * qa[r];
                y1 += dws[DIM + c] * qa[r];
                y2 += dws[2 * DIM + c] * qa[r];
            }
        }
        const float* tg = tgt + (size_t)n * 3 * HW + hw0 + tid;
        float e0 = y0 - tg[0];
        float e1 = y1 - tg[HW];
        float e2 = y2 - tg[2 * HW];
        my_vq = vq;
        my_rc = e0 * e0 + e1 * e1 + e2 * e2;
    }
    __syncthreads();
    float* sv = (float*)(sm + RED_OFF);
    float* sr = sv + 256;
    sv[tid] = my_vq;
    sr[tid] = my_rc;
    __syncthreads();
    for (int s = 128; s > 0; s >>= 1) {
        if (tid < s) { sv[tid] += sv[tid + s]; sr[tid] += sr[tid + s]; }
        __syncthreads();
    }
    if (tid == 0) {
        g_partial[blk] = sv[0];
        g_partial[NBLOCKS + blk] = sr[0];
    }
}

// ---------------- deterministic finalize (shfl-based) ----------------
__global__ void vq_finalize(float* __restrict__ out, int out_size) {
    __shared__ float wv[8], wr[8];
    int t = threadIdx.x;              // 256
    int lane = t & 31, w = t >> 5;
    float v = g_partial[t];
    float r = g_partial[NBLOCKS + t];
#pragma unroll
    for (int off = 16; off > 0; off >>= 1) {
        v += __shfl_xor_sync(0xFFFFFFFFu, v, off);
        r += __shfl_xor_sync(0xFFFFFFFFu, r, off);
    }
    if (lane == 0) { wv[w] = v; wr[w] = r; }
    __syncthreads();
    for (int idx = t; idx < out_size; idx += blockDim.x)
        if (idx >= 3) out[idx] = 0.f;
    if (t == 0) {
        float sv = 0.f, sr = 0.f;
#pragma unroll
        for (int k = 0; k < 8; ++k) { sv += wv[k]; sr += wr[k]; }
        float vq_loss = 2.0f * sv / (float)(NB * DIM * HW);
        float recon = sr / (float)(NB * 3 * HW);
        if (out_size > 0) out[0] = vq_loss + recon;
        if (out_size > 1) out[1] = vq_loss;
        if (out_size > 2) out[2] = recon;
    }
}

extern "C" void kernel_launch(void* const* d_in, const int* in_sizes, int n_in,
                              void* d_out, int out_size) {
    const float* lat = (const float*)d_in[0];
    const float* tgt = (const float*)d_in[1];
    const float* cb  = (const float*)d_in[2];
    const float* dw  = (const float*)d_in[3];
    const float* db  = (const float*)d_in[4];
    float* out = (float*)d_out;

    vq_prep<<<128, 256>>>(cb);

    cudaFuncSetAttribute(vq_main, cudaFuncAttributeMaxDynamicSharedMemorySize, SMEM_TOTAL);
    vq_main<<<NBLOCKS, 256, SMEM_TOTAL>>>(lat, tgt, cb, dw, db);

    vq_finalize<<<1, NBLOCKS>>>(out, out_size);
}

// round 8
// speedup vs baseline: 3.2204x; 1.1022x over previous
#include <cuda_runtime.h>
#include <cuda_fp16.h>
#include <cstdint>

// ---------------- problem constants ----------------
#define NB      32
#define DIM     64
#define HW      1024
#define KCODES  2048
#define TOK_TILE 128
#define NBLOCKS  256          // TOKENS / TOK_TILE
#define NTILES   16           // KCODES / 128
#define BMARG    0.35f        // conservative |d2' - d_hi| bound (rigorous ~0.14)
#define WLIST    512          // per-warp candidate capacity

// ---------------- dynamic smem layout (bytes) ----------------
#define A_STRIDE 132
#define A_OFF    0u                       // fp32 A [64][132]  (33792 B)
#define B_OFF    33792u                   // 2 buffers x 16KB hi-only frag tiles
#define B_BUF    16384u
#define CN_OFF   66560u                   // 2 x 128 floats
#define DW_OFF   67584u                   // 192 floats
#define DB_OFF   68352u                   // 4 floats
#define CNT_OFF  68368u                   // 8 u32 per-warp counters
#define LIST_OFF 68400u                   // 8 x WLIST u32
#define TOKMIN_OFF 84784u                 // 128 u64
#define RED_OFF  85808u                   // 512 floats
#define SMEM_TOTAL 88064u

__device__ float g_cnorm[KCODES];
__device__ float g_partial[2 * NBLOCKS];
__device__ unsigned int g_done = 0;
// fragment-ordered fp16 HI codebook: per tile 4096 u32
// addr = fg*64 + lane*2 + {0,1}   (fg = kk*16 + nt; {0,1} = b0/b1 regs)
__device__ uint32_t g_cbf[NTILES * 4096];

// ---------------- helpers ----------------
__device__ __forceinline__ uint32_t smem_u32(const void* p) {
    uint32_t a;
    asm("{ .reg .u64 t; cvta.to.shared.u64 t, %1; cvt.u32.u64 %0, t; }" : "=r"(a) : "l"(p));
    return a;
}
__device__ __forceinline__ uint32_t packh2(float x, float y) {
    __half2 h = __floats2half2_rn(x, y);
    return *reinterpret_cast<uint32_t*>(&h);
}
__device__ __forceinline__ void mma_f16(float* d, const uint32_t* a,
                                        uint32_t b0, uint32_t b1) {
    asm volatile(
        "mma.sync.aligned.m16n8k16.row.col.f32.f16.f16.f32 "
        "{%0,%1,%2,%3}, {%4,%5,%6,%7}, {%8,%9}, {%0,%1,%2,%3};"
        : "+f"(d[0]), "+f"(d[1]), "+f"(d[2]), "+f"(d[3])
        : "r"(a[0]), "r"(a[1]), "r"(a[2]), "r"(a[3]), "r"(b0), "r"(b1));
}
__device__ __forceinline__ void cp16(uint32_t s, const void* g) {
    asm volatile("cp.async.cg.shared.global [%0], [%1], 16;" :: "r"(s), "l"(g));
}
__device__ __forceinline__ void cp_commit() {
    asm volatile("cp.async.commit_group;" ::: "memory");
}
__device__ __forceinline__ void cp_wait0() {
    asm volatile("cp.async.wait_group 0;" ::: "memory");
}
__device__ __forceinline__ uint32_t fkey(float v) {
    uint32_t b = __float_as_uint(v);
    return (b & 0x80000000u) ? ~b : (b | 0x80000000u);
}

// ---------------- prep: codebook norms + fp16 hi fragment pack ----------------
__global__ void __launch_bounds__(256) vq_prep(const float* __restrict__ cb) {
    int blk = blockIdx.x;
    int tile = blk >> 3;
    int sub = blk & 7;
    int tid = threadIdx.x;
    int lane = tid & 31;
    int grp  = tid >> 5;                  // 0..7

    if (tid < 16) {
        int k = tile * 128 + sub * 16 + tid;
        const float* r = cb + (size_t)k * DIM;
        float s = 0.f;
#pragma unroll
        for (int c4 = 0; c4 < DIM / 4; ++c4) {
            float4 v = *(const float4*)(r + c4 * 4);
            s += v.x * v.x + v.y * v.y + v.z * v.z + v.w * v.w;
        }
        g_cnorm[k] = s;
    }

    uint32_t* dsth = g_cbf + (size_t)tile * 4096;
    int fg = sub * 8 + grp;               // 0..63 = kk*16 + nt
    int kk = fg >> 4;
    int nt = fg & 15;
    int code = tile * 128 + nt * 8 + (lane >> 2);
    int k0 = kk * 16 + (lane & 3) * 2;
    const float* row = cb + (size_t)code * DIM;
    dsth[fg * 64 + lane * 2]     = packh2(row[k0], row[k0 + 1]);
    dsth[fg * 64 + lane * 2 + 1] = packh2(row[k0 + 8], row[k0 + 9]);
}

// ---------------- main kernel (finalize folded in) ----------------
__global__ void __launch_bounds__(256, 2)
vq_main(const float* __restrict__ lat, const float* __restrict__ tgt,
        const float* __restrict__ cb, const float* __restrict__ dw,
        const float* __restrict__ db, float* __restrict__ out, int out_size) {
    extern __shared__ char sm[];
    float* As = (float*)(sm + A_OFF);
    const uint32_t smem_base = smem_u32(sm);
    uint32_t* scnt = (uint32_t*)(sm + CNT_OFF);
    unsigned long long* tokmin = (unsigned long long*)(sm + TOKMIN_OFF);
    const int tid = threadIdx.x;
    const int lane = tid & 31;
    const int w = tid >> 5;
    const int gid = lane >> 2;           // 0..7  token-row group
    const int tig = lane & 3;            // 0..3  col group
    const int blk = blockIdx.x;
    const int n = blk >> 3;
    const int hw0 = (blk & 7) * TOK_TILE;
    uint32_t* wl = (uint32_t*)(sm + LIST_OFF) + w * WLIST;

    if (tid < 192) ((float*)(sm + DW_OFF))[tid] = dw[tid];
    if (tid < 3)   ((float*)(sm + DB_OFF))[tid] = db[tid];
    if (tid < 8)   scnt[tid] = 0u;
    if (tid < 128) tokmin[tid] = ~0ull;

    // ---- stage A (fp32) [k][token] ----
    const float* latbase = lat + (size_t)n * DIM * HW + hw0;
    {
        int tl = tid & 31;
        int cgrp = tid >> 5;
#pragma unroll
        for (int p = 0; p < 8; ++p) {
            int c = p * 8 + cgrp;
            float4 v = *(const float4*)(latbase + (size_t)c * HW + tl * 4);
            *(float4*)&As[c * A_STRIDE + tl * 4] = v;
        }
    }

    // ---- preload B tile 0 + cn tile 0 ----
    {
        const float4* src = (const float4*)(g_cbf);
        uint32_t dst = smem_base + B_OFF;
#pragma unroll 4
        for (int idx = tid; idx < 1024; idx += 256)
            cp16(dst + (uint32_t)idx * 16u, src + idx);
        if (tid < 32)
            cp16(smem_base + CN_OFF + (uint32_t)tid * 16u,
                 ((const float4*)g_cnorm) + tid);
        cp_commit();
    }
    cp_wait0();
    __syncthreads();

    // ---- resident A hi fragments ----
    uint32_t ah[4][4];
    const int t0 = w * 16 + gid;
#pragma unroll
    for (int kk = 0; kk < 4; ++kk) {
        int k0 = kk * 16 + tig * 2;
        ah[kk][0] = packh2(As[(k0 + 0) * A_STRIDE + t0],     As[(k0 + 1) * A_STRIDE + t0]);
        ah[kk][1] = packh2(As[(k0 + 0) * A_STRIDE + t0 + 8], As[(k0 + 1) * A_STRIDE + t0 + 8]);
        ah[kk][2] = packh2(As[(k0 + 8) * A_STRIDE + t0],     As[(k0 + 9) * A_STRIDE + t0]);
        ah[kk][3] = packh2(As[(k0 + 8) * A_STRIDE + t0 + 8], As[(k0 + 9) * A_STRIDE + t0 + 8]);
    }

    float minv0 = 3.4e38f, minv1 = 3.4e38f;

    // 17 iterations: tiles 0..15, then tile 0 again (appends enabled from i=1)
    for (int i = 0; i <= NTILES; ++i) {
        int cur = i & 1;
        if (i < NTILES) {
            int nxt = (i + 1 == NTILES) ? 0 : i + 1;
            const float4* src = (const float4*)(g_cbf + (size_t)nxt * 4096);
            uint32_t dst = smem_base + B_OFF + (uint32_t)(cur ^ 1) * B_BUF;
#pragma unroll 4
            for (int idx = tid; idx < 1024; idx += 256)
                cp16(dst + (uint32_t)idx * 16u, src + idx);
            if (tid < 32)
                cp16(smem_base + CN_OFF + (uint32_t)(cur ^ 1) * 512u + (uint32_t)tid * 16u,
                     ((const float4*)(g_cnorm + nxt * 128)) + tid);
            cp_commit();
        }

        const char* smB = sm + B_OFF + (uint32_t)cur * B_BUF;
        const float* cns = (const float*)(sm + CN_OFF + (uint32_t)cur * 512u);
        const int ti = (i == NTILES) ? 0 : i;
        const int cbase = ti * 128;
        const bool appending = (i > 0);

#pragma unroll
        for (int nt = 0; nt < 16; nt += 2) {
            float dA0[4] = {0.f, 0.f, 0.f, 0.f};
            float dA1[4] = {0.f, 0.f, 0.f, 0.f};
            float dB0[4] = {0.f, 0.f, 0.f, 0.f};
            float dB1[4] = {0.f, 0.f, 0.f, 0.f};
            uint2 bA[4], bB[4];
#pragma unroll
            for (int kk = 0; kk < 4; ++kk) {
                bA[kk] = *(const uint2*)(smB + ((size_t)(kk * 16 + nt) * 64 + lane * 2) * 4);
                bB[kk] = *(const uint2*)(smB + ((size_t)(kk * 16 + nt + 1) * 64 + lane * 2) * 4);
            }
            mma_f16(dA0, ah[0], bA[0].x, bA[0].y);
            mma_f16(dB0, ah[0], bB[0].x, bB[0].y);
            mma_f16(dA1, ah[2], bA[2].x, bA[2].y);
            mma_f16(dB1, ah[2], bB[2].x, bB[2].y);
            mma_f16(dA0, ah[1], bA[1].x, bA[1].y);
            mma_f16(dB0, ah[1], bB[1].x, bB[1].y);
            mma_f16(dA1, ah[3], bA[3].x, bA[3].y);
            mma_f16(dB1, ah[3], bB[3].x, bB[3].y);

            float2 cnA = *(const float2*)(cns + nt * 8 + tig * 2);
            float2 cnB = *(const float2*)(cns + (nt + 1) * 8 + tig * 2);
            int cA = cbase + nt * 8 + tig * 2;
            int cB = cA + 8;
            float vA0 = fmaf(-2.f, dA0[0] + dA1[0], cnA.x);
            float vA1 = fmaf(-2.f, dA0[1] + dA1[1], cnA.y);
            float vA2 = fmaf(-2.f, dA0[2] + dA1[2], cnA.x);
            float vA3 = fmaf(-2.f, dA0[3] + dA1[3], cnA.y);
            float vB0 = fmaf(-2.f, dB0[0] + dB1[0], cnB.x);
            float vB1 = fmaf(-2.f, dB0[1] + dB1[1], cnB.y);
            float vB2 = fmaf(-2.f, dB0[2] + dB1[2], cnB.x);
            float vB3 = fmaf(-2.f, dB0[3] + dB1[3], cnB.y);

            float lim0 = minv0 + BMARG, lim1 = minv1 + BMARG;
            bool pass = (vA0 < lim0) | (vA1 < lim0) | (vA2 < lim1) | (vA3 < lim1)
                      | (vB0 < lim0) | (vB1 < lim0) | (vB2 < lim1) | (vB3 < lim1);
            if (appending) {
                if (__any_sync(0xFFFFFFFFu, pass)) {
                    if (vA0 < lim0) { uint32_t p = atomicAdd(&scnt[w], 1u); if (p < WLIST) wl[p] = ((uint32_t)t0 << 11) | (uint32_t)cA; }
                    if (vA1 < lim0) { uint32_t p = atomicAdd(&scnt[w], 1u); if (p < WLIST) wl[p] = ((uint32_t)t0 << 11) | (uint32_t)(cA + 1); }
                    if (vA2 < lim1) { uint32_t p = atomicAdd(&scnt[w], 1u); if (p < WLIST) wl[p] = ((uint32_t)(t0 + 8) << 11) | (uint32_t)cA; }
                    if (vA3 < lim1) { uint32_t p = atomicAdd(&scnt[w], 1u); if (p < WLIST) wl[p] = ((uint32_t)(t0 + 8) << 11) | (uint32_t)(cA + 1); }
                    if (vB0 < lim0) { uint32_t p = atomicAdd(&scnt[w], 1u); if (p < WLIST) wl[p] = ((uint32_t)t0 << 11) | (uint32_t)cB; }
                    if (vB1 < lim0) { uint32_t p = atomicAdd(&scnt[w], 1u); if (p < WLIST) wl[p] = ((uint32_t)t0 << 11) | (uint32_t)(cB + 1); }
                    if (vB2 < lim1) { uint32_t p = atomicAdd(&scnt[w], 1u); if (p < WLIST) wl[p] = ((uint32_t)(t0 + 8) << 11) | (uint32_t)cB; }
                    if (vB3 < lim1) { uint32_t p = atomicAdd(&scnt[w], 1u); if (p < WLIST) wl[p] = ((uint32_t)(t0 + 8) << 11) | (uint32_t)(cB + 1); }
                }
            }
            minv0 = fminf(minv0, fminf(fminf(vA0, vA1), fminf(vB0, vB1)));
            minv1 = fminf(minv1, fminf(fminf(vA2, vA3), fminf(vB2, vB3)));
        }
        // combine running min across the 4 col-threads of each token row
        minv0 = fminf(minv0, __shfl_xor_sync(0xFFFFFFFFu, minv0, 1));
        minv0 = fminf(minv0, __shfl_xor_sync(0xFFFFFFFFu, minv0, 2));
        minv1 = fminf(minv1, __shfl_xor_sync(0xFFFFFFFFu, minv1, 1));
        minv1 = fminf(minv1, __shfl_xor_sync(0xFFFFFFFFu, minv1, 2));

        cp_wait0();
        __syncthreads();
    }

    // ---- exact fp32 refinement (each warp refines its own list) ----
    {
        uint32_t mycnt = scnt[w];
        if (mycnt > WLIST) mycnt = WLIST;
        for (uint32_t idx = lane; idx < mycnt; idx += 32) {
            uint32_t e = wl[idx];
            int t = (int)(e >> 11);
            int c = (int)(e & 2047u);
            const float4* er = (const float4*)(cb + (size_t)c * DIM);
            float dot = 0.f;
#pragma unroll
            for (int k4 = 0; k4 < 16; ++k4) {
                float4 ev = er[k4];
                dot += ev.x * As[(k4 * 4 + 0) * A_STRIDE + t]
                     + ev.y * As[(k4 * 4 + 1) * A_STRIDE + t]
                     + ev.z * As[(k4 * 4 + 2) * A_STRIDE + t]
                     + ev.w * As[(k4 * 4 + 3) * A_STRIDE + t];
            }
            float val = g_cnorm[c] - 2.0f * dot;
            unsigned long long pk = ((unsigned long long)fkey(val) << 32) | (unsigned)c;
            atomicMin(&tokmin[t], pk);
        }
    }
    __syncthreads();

    // ---- exact fp32 epilogue ----
    float my_vq = 0.f, my_rc = 0.f;
    if (tid < TOK_TILE) {
        int bi = (int)(tokmin[tid] & 0xFFFFFFFFu);
        const float* q = cb + (size_t)bi * DIM;
        const float* dws = (const float*)(sm + DW_OFF);
        const float* dbs = (const float*)(sm + DB_OFF);
        float y0 = dbs[0], y1 = dbs[1], y2 = dbs[2];
        float vq = 0.f;
#pragma unroll
        for (int c4 = 0; c4 < DIM / 4; ++c4) {
            float4 qv = *(const float4*)(q + c4 * 4);
            float qa[4] = {qv.x, qv.y, qv.z, qv.w};
#pragma unroll
            for (int r = 0; r < 4; ++r) {
                int c = c4 * 4 + r;
                float xc = As[c * A_STRIDE + tid];
                float dd = xc - qa[r];
                vq += dd * dd;
                y0 += dws[c] * qa[r];
                y1 += dws[DIM + c] * qa[r];
                y2 += dws[2 * DIM + c] * qa[r];
            }
        }
        const float* tg = tgt + (size_t)n * 3 * HW + hw0 + tid;
        float e0 = y0 - tg[0];
        float e1 = y1 - tg[HW];
        float e2 = y2 - tg[2 * HW];
        my_vq = vq;
        my_rc = e0 * e0 + e1 * e1 + e2 * e2;
    }
    __syncthreads();
    float* sv = (float*)(sm + RED_OFF);
    float* sr = sv + 256;
    sv[tid] = my_vq;
    sr[tid] = my_rc;
    __syncthreads();
    for (int s = 128; s > 0; s >>= 1) {
        if (tid < s) { sv[tid] += sv[tid + s]; sr[tid] += sr[tid + s]; }
        __syncthreads();
    }
    if (tid == 0) {
        g_partial[blk] = sv[0];
        g_partial[NBLOCKS + blk] = sr[0];
    }

    // ---- last-block finalize (deterministic) ----
    __shared__ bool s_last;
    __threadfence();
    if (tid == 0) {
        unsigned v = atomicAdd(&g_done, 1u);
        s_last = (v == NBLOCKS - 1);
    }
    __syncthreads();
    if (s_last) {
        float v = g_partial[tid];
        float r = g_partial[NBLOCKS + tid];
        __syncthreads();
        sv[tid] = v;
        sr[tid] = r;
        __syncthreads();
        for (int s = 128; s > 0; s >>= 1) {
            if (tid < s) { sv[tid] += sv[tid + s]; sr[tid] += sr[tid + s]; }
            __syncthreads();
        }
        for (int idx = tid; idx < out_size; idx += 256)
            if (idx >= 3) out[idx] = 0.f;
        if (tid == 0) {
            float vq_loss = 2.0f * sv[0] / (float)(NB * DIM * HW);
            float recon = sr[0] / (float)(NB * 3 * HW);
            if (out_size > 0) out[0] = vq_loss + recon;
            if (out_size > 1) out[1] = vq_loss;
            if (out_size > 2) out[2] = recon;
            g_done = 0;   // reset for next launch/replay
        }
    }
}

extern "C" void kernel_launch(void* const* d_in, const int* in_sizes, int n_in,
                              void* d_out, int out_size) {
    const float* lat = (const float*)d_in[0];
    const float* tgt = (const float*)d_in[1];
    const float* cb  = (const float*)d_in[2];
    const float* dw  = (const float*)d_in[3];
    const float* db  = (const float*)d_in[4];
    float* out = (float*)d_out;

    vq_prep<<<128, 256>>>(cb);

    cudaFuncSetAttribute(vq_main, cudaFuncAttributeMaxDynamicSharedMemorySize, SMEM_TOTAL);
    vq_main<<<NBLOCKS, 256, SMEM_TOTAL>>>(lat, tgt, cb, dw, db, out, out_size);
}